// round 13
// baseline (speedup 1.0000x reference)
#include <cuda_runtime.h>
#include <cuda_fp16.h>
#include <cstdint>

#define TOKENS   8192
#define DIM      512
#define FDIM     128
#define NLEAF    8
#define BM       128
#define MAXTILES 16
#define THREADS  512
#define TOTAL_CTAS (NLEAF * MAXTILES)

// ---------------- scratch ----------------
__device__ int g_count[NLEAF];          // zero-init at load; re-zeroed by ffn's last CTA
__device__ int g_done;                  // ffn completion counter (self-resetting)
__device__ int g_list[NLEAF * TOKENS];
__device__ __half g_x_hi[TOKENS * DIM];
__device__ __half g_x_lo[TOKENS * DIM];
// W1 transposed fp16: [leaf][n=256][k=512]; n<128 -> w1a col n, n>=128 -> w1b col n-128
__device__ __half g_w1t[NLEAF * 256 * 512];
// W2 transposed fp16: [leaf][n=512][k=128]
__device__ __half g_w2t[NLEAF * 512 * 128];

__device__ __forceinline__ uint32_t smem_u32(const void* p) {
    uint32_t a;
    asm("{ .reg .u64 t; cvta.to.shared.u64 t, %1; cvt.u32.u64 %0, t; }" : "=r"(a) : "l"(p));
    return a;
}
__device__ __forceinline__ uint32_t sw128(uint32_t off) { return off ^ ((off >> 3) & 0x70); }

__device__ __forceinline__ void split_f16(float v, __half& h, __half& l) {
    h = __float2half(v);
    l = __float2half(v - __half2float(h));
}
__device__ __forceinline__ uint32_t pack_f16x2(__half a, __half b) {
    union { __half h[2]; uint32_t u; } t;
    t.h[0] = a; t.h[1] = b;
    return t.u;
}

__device__ __forceinline__ void cpa16(uint32_t dst, const void* src) {
    asm volatile("cp.async.cg.shared.global [%0], [%1], 16;" :: "r"(dst), "l"(src) : "memory");
}
#define CP_COMMIT() asm volatile("cp.async.commit_group;" ::: "memory")
#define CP_WAIT(n)  asm volatile("cp.async.wait_group %0;" :: "n"(n) : "memory")

#define LDSM4(r, a)                                                                   \
    asm volatile("ldmatrix.sync.aligned.m8n8.x4.shared.b16 {%0,%1,%2,%3}, [%4];"     \
        : "=r"((r)[0]), "=r"((r)[1]), "=r"((r)[2]), "=r"((r)[3]) : "r"(a))

__device__ __forceinline__ void mma_f16(float* d, const uint32_t* a, uint32_t b0, uint32_t b1) {
    asm volatile(
        "mma.sync.aligned.m16n8k16.row.col.f32.f16.f16.f32 "
        "{%0,%1,%2,%3},{%4,%5,%6,%7},{%8,%9},{%0,%1,%2,%3};"
        : "+f"(d[0]), "+f"(d[1]), "+f"(d[2]), "+f"(d[3])
        : "r"(a[0]), "r"(a[1]), "r"(a[2]), "r"(a[3]), "r"(b0), "r"(b1));
}

// Fused 2-pass chunk, warp tile M32xN64: per kof -> 8 LDSM4, 32 HMMA (balanced).
__device__ __forceinline__ void run_fused(
    float acc[2][8][4], uint32_t AH, uint32_t AL, uint32_t B,
    uint32_t arow0, const int br[4], int a_kad, int b_kad)
{
    #pragma unroll
    for (int kof = 0; kof < 64; kof += 16) {
        uint32_t ah[2][4], al[2][4], bf[4][4];
        #pragma unroll
        for (int mt = 0; mt < 2; mt++) {
            const uint32_t ao = sw128(arow0 + mt * 2048 + (kof + a_kad) * 2);
            LDSM4(ah[mt], AH + ao);
            LDSM4(al[mt], AL + ao);
        }
        #pragma unroll
        for (int nt = 0; nt < 4; nt++)
            LDSM4(bf[nt], B + sw128((uint32_t)(br[nt] * 128 + (kof + b_kad) * 2)));
        #pragma unroll
        for (int pass = 0; pass < 2; pass++) {
            #pragma unroll
            for (int mt = 0; mt < 2; mt++) {
                const uint32_t* af = pass ? al[mt] : ah[mt];
                #pragma unroll
                for (int nt = 0; nt < 4; nt++) {
                    mma_f16(acc[mt][2 * nt],     af, bf[nt][0], bf[nt][1]);
                    mma_f16(acc[mt][2 * nt + 1], af, bf[nt][2], bf[nt][3]);
                }
            }
        }
    }
}

__device__ __forceinline__ float warp_sum(float v) {
    #pragma unroll
    for (int o = 16; o > 0; o >>= 1) v += __shfl_xor_sync(0xFFFFFFFFu, v, o);
    return v;
}

// ---------------- fused prep (W transpose->fp16) + routing + X split ----------------
// blocks [0,512): W1; [512,1024): W2; [1024,2048): route (8 tokens per block). 256 threads.
__global__ void prep_route_kernel(
    const float* __restrict__ w1a, const float* __restrict__ w1b, const float* __restrict__ w2,
    const float* __restrict__ x,
    const float* __restrict__ wn0, const float* __restrict__ bn0,
    const float* __restrict__ wn1, const float* __restrict__ bn1,
    const float* __restrict__ wn2, const float* __restrict__ bn2)
{
    const int bid = blockIdx.x;
    const int tid = threadIdx.x;

    if (bid < 512) {        // ---- W1: leaf/kt/ft ----
        const int leaf = bid >> 6, rem = bid & 63, kt = rem >> 2, ft = rem & 3;
        __shared__ float ta[32][33], tb[32][33];
        {
            int r = tid >> 3, cq = tid & 7;
            size_t src = ((size_t)leaf * 512 + kt * 32 + r) * 128 + ft * 32 + cq * 4;
            float4 va = *(const float4*)(w1a + src);
            float4 vb = *(const float4*)(w1b + src);
            ta[r][cq*4+0]=va.x; ta[r][cq*4+1]=va.y; ta[r][cq*4+2]=va.z; ta[r][cq*4+3]=va.w;
            tb[r][cq*4+0]=vb.x; tb[r][cq*4+1]=vb.y; tb[r][cq*4+2]=vb.z; tb[r][cq*4+3]=vb.w;
        }
        __syncthreads();
        {
            int n = tid >> 2, kq = tid & 3;
            int side = n >> 5, fl = n & 31;
            union { __half h[8]; uint4 u; } h8;
            #pragma unroll
            for (int j = 0; j < 8; j++) {
                float v = side ? tb[kq * 8 + j][fl] : ta[kq * 8 + j][fl];
                h8.h[j] = __float2half(v);
            }
            int orow = side ? (128 + ft * 32 + fl) : (ft * 32 + fl);
            size_t off = ((size_t)leaf * 256 + orow) * 512 + kt * 32 + kq * 8;
            *(uint4*)(g_w1t + off) = h8.u;
        }
    } else if (bid < 1024) {    // ---- W2: leaf/dt/kt ----
        const int b2i = bid - 512;
        const int leaf = b2i >> 6, rem = b2i & 63, dt = rem >> 2, kt = rem & 3;
        __shared__ float t[32][33];
        {
            int r = tid >> 3, cq = tid & 7;
            size_t src = ((size_t)leaf * 128 + kt * 32 + r) * 512 + dt * 32 + cq * 4;
            float4 v = *(const float4*)(w2 + src);
            t[r][cq*4+0]=v.x; t[r][cq*4+1]=v.y; t[r][cq*4+2]=v.z; t[r][cq*4+3]=v.w;
        }
        __syncthreads();
        {
            int n = tid >> 3, kq = tid & 7;
            union { __half h[4]; uint2 u; } h4;
            #pragma unroll
            for (int j = 0; j < 4; j++) h4.h[j] = __float2half(t[kq * 4 + j][n]);
            size_t orow = ((size_t)leaf * 512 + dt * 32 + n) * 128 + kt * 32 + kq * 4;
            *(uint2*)(g_w2t + orow) = h4.u;
        }
    } else {                // ---- route: one warp per token + X split ----
        const int gwarp = (bid - 1024) * 8 + (tid >> 5);
        const int lane  = tid & 31;

        const float4* xr4 = (const float4*)(x + (size_t)gwarp * DIM);
        float4 xv[4];
        #pragma unroll
        for (int i = 0; i < 4; i++) xv[i] = xr4[lane + i * 32];

        {
            __half* xh = g_x_hi + (size_t)gwarp * DIM;
            __half* xl = g_x_lo + (size_t)gwarp * DIM;
            #pragma unroll
            for (int i = 0; i < 4; i++) {
                float v[4] = { xv[i].x, xv[i].y, xv[i].z, xv[i].w };
                union { __half h[4]; uint2 u; } h4, l4;
                #pragma unroll
                for (int j = 0; j < 4; j++) split_f16(v[j], h4.h[j], l4.h[j]);
                *(uint2*)(xh + (lane + i * 32) * 4) = h4.u;
                *(uint2*)(xl + (lane + i * 32) * 4) = l4.u;
            }
        }

        float s = 0.f;
        #pragma unroll
        for (int i = 0; i < 4; i++) {
            int base = (lane + i * 32) * 4;
            s += xv[i].x * wn0[base + 0] + xv[i].y * wn0[base + 1]
               + xv[i].z * wn0[base + 2] + xv[i].w * wn0[base + 3];
        }
        s = warp_sum(s) + bn0[0];
        int node = (s > 0.f) ? 0 : 1;

        s = 0.f;
        #pragma unroll
        for (int i = 0; i < 4; i++) {
            int base = (lane + i * 32) * 4;
            s += xv[i].x * wn1[(base + 0) * 2 + node] + xv[i].y * wn1[(base + 1) * 2 + node]
               + xv[i].z * wn1[(base + 2) * 2 + node] + xv[i].w * wn1[(base + 3) * 2 + node];
        }
        s = warp_sum(s) + bn1[node];
        node = node * 2 + ((s > 0.f) ? 0 : 1);

        s = 0.f;
        #pragma unroll
        for (int i = 0; i < 4; i++) {
            int base = (lane + i * 32) * 4;
            s += xv[i].x * wn2[(base + 0) * 4 + node] + xv[i].y * wn2[(base + 1) * 4 + node]
               + xv[i].z * wn2[(base + 2) * 4 + node] + xv[i].w * wn2[(base + 3) * 4 + node];
        }
        s = warp_sum(s) + bn2[node];
        int leaf = node * 2 + ((s > 0.f) ? 0 : 1);

        if (lane == 0) {
            int pos = atomicAdd(&g_count[leaf], 1);
            g_list[leaf * TOKENS + pos] = gwarp;
        }
    }
}

// ---------------- SMEM layout: BM=128, 2-stage pipeline ----------------
#define SM_ROWTOK  0                        // 512B
#define SM_B1A     512
#define SM_B1B     1024
#define SM_B2      1536                     // 2KB -> ends 3584
#define SM_X       4096                     // 2 buf x (hi 16KB | lo 16KB) = 64KB
#define SM_W       69632                    // 2 buf x 32KB = 64KB
#define SM_H       135168                   // hi0,hi1 (32KB) then lo0,lo1 (32KB)
#define SMEM_TOTAL 200704

#define XHI(p) (sb + SM_X + (p) * 32768)
#define XLO(p) (sb + SM_X + (p) * 32768 + 16384)
#define WB(p)  (sb + SM_W + (p) * 32768)
#define HHI(k) (sb + SM_H + (k) * 16384)
#define HLO(k) (sb + SM_H + 32768 + (k) * 16384)

__device__ __forceinline__ void cta_done_and_maybe_reset() {
    int old = atomicAdd(&g_done, 1);
    if (old == TOTAL_CTAS - 1) {
        #pragma unroll
        for (int i = 0; i < NLEAF; i++) g_count[i] = 0;
        __threadfence();
        g_done = 0;
    }
}

// ---------------- fused leaf FFN: BM=128, 16 warps, M32xN64, 1 sync/chunk ----------------
__global__ void __launch_bounds__(THREADS, 1)
ffn_kernel(const float* __restrict__ b1a, const float* __restrict__ b1b,
           const float* __restrict__ b2,  float* __restrict__ out)
{
    extern __shared__ char smem[];
    const uint32_t sb = smem_u32(smem);
    const int tid  = threadIdx.x;
    const int wid  = tid >> 5;
    const int lane = tid & 31;

    const int leaf  = blockIdx.x;
    const int cnt   = g_count[leaf];
    const int start = blockIdx.y * BM;
    if (start >= cnt) {
        __syncthreads();
        if (tid == 0) cta_done_and_maybe_reset();
        return;
    }
    const int rows = min(BM, cnt - start);
    const int* list = g_list + leaf * TOKENS + start;

    int* rowTok = (int*)(smem + SM_ROWTOK);
    if (tid < BM) rowTok[tid] = list[min(tid, rows - 1)];
    {
        float* sB1a = (float*)(smem + SM_B1A);
        float* sB1b = (float*)(smem + SM_B1B);
        float* sB2  = (float*)(smem + SM_B2);
        if (tid < FDIM) { sB1a[tid] = b1a[leaf * FDIM + tid]; sB1b[tid] = b1b[leaf * FDIM + tid]; }
        if (tid < DIM)  sB2[tid] = b2[leaf * DIM + tid];
    }
    __syncthreads();

    const int wm = wid & 3;        // m-block: rows 32*wm..+31 (2 m16 tiles)
    const int wn = wid >> 2;       // n-block 0..3
    const int gid = lane >> 2, tig = lane & 3;
    const int a_row = lane & 15;
    const int a_kad = (lane & 16) >> 1;
    const int b_row = (lane & 7) | ((lane >> 1) & 8);
    const int b_kad = lane & 8;
    const uint32_t arow0 = (uint32_t)((32 * wm + a_row) * 128);

    // GEMM1: warp covers a-cols [32wn,32wn+32) (nt 0,1) + matching b-cols (nt 2,3)
    const int br1[4] = { 32 * wn + b_row, 32 * wn + 16 + b_row,
                         128 + 32 * wn + b_row, 128 + 32 * wn + 16 + b_row };
    const int br2[4] = { 64 * wn + b_row, 64 * wn + 16 + b_row,
                         64 * wn + 32 + b_row, 64 * wn + 48 + b_row };

    // X loader: 128 rows x 128B per half; 512 threads -> rows tid>>3 and tid>>3+64
    const int xq = tid & 7;
    const size_t tokA = (size_t)rowTok[tid >> 3] * DIM;
    const size_t tokB = (size_t)rowTok[(tid >> 3) + 64] * DIM;
    const __half* w1base = g_w1t + (size_t)leaf * 256 * DIM;
    const __half* w2base = g_w2t + (size_t)leaf * 512 * FDIM;

    auto issue = [&](int c) {
        const int p = c & 1;
        if (c < 8) {
            const int k0 = c * 64;
            {
                const int ra = tid >> 3;
                uint32_t soA = sw128((uint32_t)(ra * 128 + xq * 16));
                uint32_t soB = sw128((uint32_t)((ra + 64) * 128 + xq * 16));
                cpa16(XHI(p) + soA, g_x_hi + tokA + k0 + xq * 8);
                cpa16(XLO(p) + soA, g_x_lo + tokA + k0 + xq * 8);
                cpa16(XHI(p) + soB, g_x_hi + tokB + k0 + xq * 8);
                cpa16(XLO(p) + soB, g_x_lo + tokB + k0 + xq * 8);
            }
            const __half* wb = w1base + k0;
            #pragma unroll
            for (int it = 0; it < 4; it++) {           // W1: 256 rows x 128B
                int idx = tid + it * THREADS;
                int wrow = idx >> 3, q = idx & 7;
                uint32_t wo = sw128((uint32_t)(wrow * 128 + q * 16));
                cpa16(WB(p) + wo, wb + (size_t)wrow * DIM + q * 8);
            }
        } else {
            const int idx4 = c - 8, nh = idx4 >> 1, c2 = idx4 & 1;
            const __half* wb = w2base + (size_t)nh * 256 * FDIM + c2 * 64;
            #pragma unroll
            for (int it = 0; it < 4; it++) {
                int idx = tid + it * THREADS;
                int wrow = idx >> 3, q = idx & 7;
                uint32_t wo = sw128((uint32_t)(wrow * 128 + q * 16));
                cpa16(WB(p) + wo, wb + (size_t)wrow * FDIM + q * 8);
            }
        }
        CP_COMMIT();
    };

    issue(0);

    // ================= phase 1: GEMM1 (chunks 0..7) =================
    {
        float acc[2][8][4];
        #pragma unroll
        for (int mt = 0; mt < 2; mt++)
            #pragma unroll
            for (int t = 0; t < 8; t++)
                #pragma unroll
                for (int j = 0; j < 4; j++) acc[mt][t][j] = 0.f;

        for (int c = 0; c < 8; c++) {
            const int p = c & 1;
            CP_WAIT(0);                      // chunk c landed (only group outstanding)
            __syncthreads();                 // all warps past run_fused(c-1)
            issue(c + 1);                    // writes buf (c+1)&1 == (c-1)&1, now free
            run_fused(acc, XHI(p), XLO(p), WB(p), arow0, br1, a_kad, b_kad);
        }

        // epilogue1: gate (a tile nt, b tile nt+2) -> H fp16 hi/lo, packed 4B stores
        const float* sB1a = (const float*)(smem + SM_B1A);
        const float* sB1b = (const float*)(smem + SM_B1B);
        #pragma unroll
        for (int mt = 0; mt < 2; mt++) {
            const int r0 = 32 * wm + 16 * mt + gid;
            #pragma unroll
            for (int nt = 0; nt < 2; nt++) {
                #pragma unroll
                for (int q = 0; q < 2; q++) {
                    const int f = 32 * wn + 16 * nt + 8 * q + 2 * tig;
                    const float* A = acc[mt][2 * nt + q];
                    const float* G = acc[mt][2 * (nt + 2) + q];
                    const float ba0 = sB1a[f], ba1 = sB1a[f + 1];
                    const float bb0 = sB1b[f], bb1 = sB1b[f + 1];
                    const float h00 = (A[0] + ba0) * (G[0] + bb0);
                    const float h01 = (A[1] + ba1) * (G[1] + bb1);
                    const float h10 = (A[2] + ba0) * (G[2] + bb0);
                    const float h11 = (A[3] + ba1) * (G[3] + bb1);
                    const int kc = f >> 6, fk = f & 63;
                    char* hh = smem + (HHI(kc) - sb);
                    char* hl = smem + (HLO(kc) - sb);
                    const uint32_t o0 = sw128((uint32_t)(r0 * 128 + fk * 2));
                    const uint32_t o1 = sw128((uint32_t)((r0 + 8) * 128 + fk * 2));
                    __half a0h, a0l, a1h, a1l, a2h, a2l, a3h, a3l;
                    split_f16(h00, a0h, a0l);  split_f16(h01, a1h, a1l);
                    split_f16(h10, a2h, a2l);  split_f16(h11, a3h, a3l);
                    *(uint32_t*)(hh + o0) = pack_f16x2(a0h, a1h);
                    *(uint32_t*)(hl + o0) = pack_f16x2(a0l, a1l);
                    *(uint32_t*)(hh + o1) = pack_f16x2(a2h, a3h);
                    *(uint32_t*)(hl + o1) = pack_f16x2(a2l, a3l);
                }
            }
        }
    }

    // ================= phase 2: GEMM2 (chunks 8..11) =================
    {
        const float* sB2 = (const float*)(smem + SM_B2);
        int c = 8;
        for (int nh = 0; nh < 2; nh++) {
            float acc2[2][8][4];
            #pragma unroll
            for (int mt = 0; mt < 2; mt++)
                #pragma unroll
                for (int t = 0; t < 8; t++)
                    #pragma unroll
                    for (int j = 0; j < 4; j++) acc2[mt][t][j] = 0.f;

            #pragma unroll
            for (int c2 = 0; c2 < 2; c2++, c++) {
                CP_WAIT(0);
                __syncthreads();             // orders H writes (c==8) and buffer reuse
                if (c + 1 < 12) issue(c + 1);
                run_fused(acc2, HHI(c2), HLO(c2), WB(c & 1), arow0, br2, a_kad, b_kad);
            }

            #pragma unroll
            for (int mt = 0; mt < 2; mt++) {
                const int r0 = 32 * wm + 16 * mt + gid;
                #pragma unroll
                for (int t = 0; t < 8; t++) {
                    const int col = nh * 256 + 64 * wn + 8 * t + 2 * tig;
                    const float c0 = sB2[col], c1 = sB2[col + 1];
                    if (r0 < rows) {
                        float2 v = { acc2[mt][t][0] + c0, acc2[mt][t][1] + c1 };
                        *(float2*)(out + (size_t)rowTok[r0] * DIM + col) = v;
                    }
                    if (r0 + 8 < rows) {
                        float2 v = { acc2[mt][t][2] + c0, acc2[mt][t][3] + c1 };
                        *(float2*)(out + (size_t)rowTok[r0 + 8] * DIM + col) = v;
                    }
                }
            }
        }
    }

    __syncthreads();
    if (tid == 0) cta_done_and_maybe_reset();
}

extern "C" void kernel_launch(void* const* d_in, const int* in_sizes, int n_in,
                              void* d_out, int out_size)
{
    const float* x   = (const float*)d_in[0];
    const float* wn0 = (const float*)d_in[2];
    const float* bn0 = (const float*)d_in[3];
    const float* wn1 = (const float*)d_in[4];
    const float* bn1 = (const float*)d_in[5];
    const float* wn2 = (const float*)d_in[6];
    const float* bn2 = (const float*)d_in[7];
    const float* w1a = (const float*)d_in[8];
    const float* b1a = (const float*)d_in[9];
    const float* w1b = (const float*)d_in[10];
    const float* b1b = (const float*)d_in[11];
    const float* w2  = (const float*)d_in[12];
    const float* b2  = (const float*)d_in[13];
    float* out = (float*)d_out;

    static_assert(SMEM_TOTAL <= 227 * 1024, "smem");
    cudaFuncSetAttribute(ffn_kernel, cudaFuncAttributeMaxDynamicSharedMemorySize, SMEM_TOTAL);

    // g_count is zero at entry: zero-initialized at module load, then re-zeroed by
    // ffn_kernel's last CTA on every launch (deterministic across graph replays).
    prep_route_kernel<<<2048, 256>>>(w1a, w1b, w2, x, wn0, bn0, wn1, bn1, wn2, bn2);
    dim3 grid(NLEAF, MAXTILES);
    ffn_kernel<<<grid, THREADS, SMEM_TOTAL>>>(b1a, b1b, b2, out);
}

// round 14
// speedup vs baseline: 1.5905x; 1.5905x over previous
#include <cuda_runtime.h>
#include <cuda_fp16.h>
#include <cstdint>

#define TOKENS   8192
#define DIM      512
#define FDIM     128
#define NLEAF    8
#define BM       64
#define MAXTILES 32
#define THREADS  512
#define TOTAL_CTAS (NLEAF * MAXTILES)

// ---------------- scratch ----------------
__device__ int g_count[NLEAF];          // zero-init at load; re-zeroed by ffn's last CTA
__device__ int g_done;                  // ffn completion counter (self-resetting)
__device__ int g_list[NLEAF * TOKENS];
__device__ __half g_x[TOKENS * DIM];    // fp16 activations
// W1 transposed fp16: [leaf][n=256][k=512]; n<128 -> w1a col n, n>=128 -> w1b col n-128
__device__ __half g_w1t[NLEAF * 256 * 512];
// W2 transposed fp16: [leaf][n=512][k=128]
__device__ __half g_w2t[NLEAF * 512 * 128];

__device__ __forceinline__ uint32_t smem_u32(const void* p) {
    uint32_t a;
    asm("{ .reg .u64 t; cvta.to.shared.u64 t, %1; cvt.u32.u64 %0, t; }" : "=r"(a) : "l"(p));
    return a;
}
__device__ __forceinline__ uint32_t sw128(uint32_t off) { return off ^ ((off >> 3) & 0x70); }

__device__ __forceinline__ uint32_t pack_f16x2(__half a, __half b) {
    union { __half h[2]; uint32_t u; } t;
    t.h[0] = a; t.h[1] = b;
    return t.u;
}

__device__ __forceinline__ void cpa16(uint32_t dst, const void* src) {
    asm volatile("cp.async.cg.shared.global [%0], [%1], 16;" :: "r"(dst), "l"(src) : "memory");
}
#define CP_COMMIT() asm volatile("cp.async.commit_group;" ::: "memory")
#define CP_WAIT(n)  asm volatile("cp.async.wait_group %0;" :: "n"(n) : "memory")

#define LDSM4(r, a)                                                                   \
    asm volatile("ldmatrix.sync.aligned.m8n8.x4.shared.b16 {%0,%1,%2,%3}, [%4];"     \
        : "=r"((r)[0]), "=r"((r)[1]), "=r"((r)[2]), "=r"((r)[3]) : "r"(a))

__device__ __forceinline__ void mma_f16(float* d, const uint32_t* a, uint32_t b0, uint32_t b1) {
    asm volatile(
        "mma.sync.aligned.m16n8k16.row.col.f32.f16.f16.f32 "
        "{%0,%1,%2,%3},{%4,%5,%6,%7},{%8,%9},{%0,%1,%2,%3};"
        : "+f"(d[0]), "+f"(d[1]), "+f"(d[2]), "+f"(d[3])
        : "r"(a[0]), "r"(a[1]), "r"(a[2]), "r"(a[3]), "r"(b0), "r"(b1));
}

// Single-pass fp16 chunk, warp tile M16xN64: per kof -> 5 LDSM4, 8 HMMA.
__device__ __forceinline__ void run_fused(
    float acc[8][4], uint32_t A, uint32_t B,
    uint32_t arow0, const int br[4], int a_kad, int b_kad)
{
    #pragma unroll
    for (int kof = 0; kof < 64; kof += 16) {
        uint32_t af[4], bf[4][4];
        LDSM4(af, A + sw128(arow0 + (kof + a_kad) * 2));
        #pragma unroll
        for (int nt = 0; nt < 4; nt++)
            LDSM4(bf[nt], B + sw128((uint32_t)(br[nt] * 128 + (kof + b_kad) * 2)));
        #pragma unroll
        for (int nt = 0; nt < 4; nt++) {
            mma_f16(acc[2 * nt],     af, bf[nt][0], bf[nt][1]);
            mma_f16(acc[2 * nt + 1], af, bf[nt][2], bf[nt][3]);
        }
    }
}

__device__ __forceinline__ float warp_sum(float v) {
    #pragma unroll
    for (int o = 16; o > 0; o >>= 1) v += __shfl_xor_sync(0xFFFFFFFFu, v, o);
    return v;
}

// ---------------- fused prep (W transpose->fp16) + routing + X fp16 ----------------
// blocks [0,512): W1; [512,1024): W2; [1024,2048): route (8 tokens per block). 256 threads.
__global__ void prep_route_kernel(
    const float* __restrict__ w1a, const float* __restrict__ w1b, const float* __restrict__ w2,
    const float* __restrict__ x,
    const float* __restrict__ wn0, const float* __restrict__ bn0,
    const float* __restrict__ wn1, const float* __restrict__ bn1,
    const float* __restrict__ wn2, const float* __restrict__ bn2)
{
    const int bid = blockIdx.x;
    const int tid = threadIdx.x;

    if (bid < 512) {        // ---- W1: leaf/kt/ft ----
        const int leaf = bid >> 6, rem = bid & 63, kt = rem >> 2, ft = rem & 3;
        __shared__ float ta[32][33], tb[32][33];
        {
            int r = tid >> 3, cq = tid & 7;
            size_t src = ((size_t)leaf * 512 + kt * 32 + r) * 128 + ft * 32 + cq * 4;
            float4 va = *(const float4*)(w1a + src);
            float4 vb = *(const float4*)(w1b + src);
            ta[r][cq*4+0]=va.x; ta[r][cq*4+1]=va.y; ta[r][cq*4+2]=va.z; ta[r][cq*4+3]=va.w;
            tb[r][cq*4+0]=vb.x; tb[r][cq*4+1]=vb.y; tb[r][cq*4+2]=vb.z; tb[r][cq*4+3]=vb.w;
        }
        __syncthreads();
        {
            int n = tid >> 2, kq = tid & 3;
            int side = n >> 5, fl = n & 31;
            union { __half h[8]; uint4 u; } h8;
            #pragma unroll
            for (int j = 0; j < 8; j++) {
                float v = side ? tb[kq * 8 + j][fl] : ta[kq * 8 + j][fl];
                h8.h[j] = __float2half(v);
            }
            int orow = side ? (128 + ft * 32 + fl) : (ft * 32 + fl);
            size_t off = ((size_t)leaf * 256 + orow) * 512 + kt * 32 + kq * 8;
            *(uint4*)(g_w1t + off) = h8.u;
        }
    } else if (bid < 1024) {    // ---- W2: leaf/dt/kt ----
        const int b2i = bid - 512;
        const int leaf = b2i >> 6, rem = b2i & 63, dt = rem >> 2, kt = rem & 3;
        __shared__ float t[32][33];
        {
            int r = tid >> 3, cq = tid & 7;
            size_t src = ((size_t)leaf * 128 + kt * 32 + r) * 512 + dt * 32 + cq * 4;
            float4 v = *(const float4*)(w2 + src);
            t[r][cq*4+0]=v.x; t[r][cq*4+1]=v.y; t[r][cq*4+2]=v.z; t[r][cq*4+3]=v.w;
        }
        __syncthreads();
        {
            int n = tid >> 3, kq = tid & 7;
            union { __half h[4]; uint2 u; } h4;
            #pragma unroll
            for (int j = 0; j < 4; j++) h4.h[j] = __float2half(t[kq * 4 + j][n]);
            size_t orow = ((size_t)leaf * 512 + dt * 32 + n) * 128 + kt * 32 + kq * 4;
            *(uint2*)(g_w2t + orow) = h4.u;
        }
    } else {                // ---- route: one warp per token + X fp16 ----
        const int gwarp = (bid - 1024) * 8 + (tid >> 5);
        const int lane  = tid & 31;

        const float4* xr4 = (const float4*)(x + (size_t)gwarp * DIM);
        float4 xv[4];
        #pragma unroll
        for (int i = 0; i < 4; i++) xv[i] = xr4[lane + i * 32];

        {
            __half* xh = g_x + (size_t)gwarp * DIM;
            #pragma unroll
            for (int i = 0; i < 4; i++) {
                union { __half h[4]; uint2 u; } h4;
                h4.h[0] = __float2half(xv[i].x);
                h4.h[1] = __float2half(xv[i].y);
                h4.h[2] = __float2half(xv[i].z);
                h4.h[3] = __float2half(xv[i].w);
                *(uint2*)(xh + (lane + i * 32) * 4) = h4.u;
            }
        }

        float s = 0.f;
        #pragma unroll
        for (int i = 0; i < 4; i++) {
            int base = (lane + i * 32) * 4;
            s += xv[i].x * wn0[base + 0] + xv[i].y * wn0[base + 1]
               + xv[i].z * wn0[base + 2] + xv[i].w * wn0[base + 3];
        }
        s = warp_sum(s) + bn0[0];
        int node = (s > 0.f) ? 0 : 1;

        s = 0.f;
        #pragma unroll
        for (int i = 0; i < 4; i++) {
            int base = (lane + i * 32) * 4;
            s += xv[i].x * wn1[(base + 0) * 2 + node] + xv[i].y * wn1[(base + 1) * 2 + node]
               + xv[i].z * wn1[(base + 2) * 2 + node] + xv[i].w * wn1[(base + 3) * 2 + node];
        }
        s = warp_sum(s) + bn1[node];
        node = node * 2 + ((s > 0.f) ? 0 : 1);

        s = 0.f;
        #pragma unroll
        for (int i = 0; i < 4; i++) {
            int base = (lane + i * 32) * 4;
            s += xv[i].x * wn2[(base + 0) * 4 + node] + xv[i].y * wn2[(base + 1) * 4 + node]
               + xv[i].z * wn2[(base + 2) * 4 + node] + xv[i].w * wn2[(base + 3) * 4 + node];
        }
        s = warp_sum(s) + bn2[node];
        int leaf = node * 2 + ((s > 0.f) ? 0 : 1);

        if (lane == 0) {
            int pos = atomicAdd(&g_count[leaf], 1);
            g_list[leaf * TOKENS + pos] = gwarp;
        }
    }
}

// ---------------- SMEM layout: 3-stage pipeline, single-precision-path fp16 ----------------
#define SM_ROWTOK  0
#define SM_B1A     256
#define SM_B1B     768
#define SM_B2      1280                     // 2KB -> ends 3328
#define SM_X       4096                     // 3 buf x 8KB = 24KB -> ends 28672
#define SM_W       28672                    // 3 buf x 32KB = 96KB -> ends 126976
#define SM_H       126976                   // 2 x 8KB = 16KB -> ends 143360
#define SMEM_TOTAL 143360

#define XB(p)  (sb + SM_X + (p) * 8192)
#define WB(p)  (sb + SM_W + (p) * 32768)
#define HB(k)  (sb + SM_H + (k) * 8192)

__device__ __forceinline__ void cta_done_and_maybe_reset() {
    int old = atomicAdd(&g_done, 1);
    if (old == TOTAL_CTAS - 1) {
        #pragma unroll
        for (int i = 0; i < NLEAF; i++) g_count[i] = 0;
        __threadfence();
        g_done = 0;
    }
}

// ---------------- fused leaf FFN: single-pass fp16, 16 warps, M16xN64 ----------------
__global__ void __launch_bounds__(THREADS, 1)
ffn_kernel(const float* __restrict__ b1a, const float* __restrict__ b1b,
           const float* __restrict__ b2,  float* __restrict__ out)
{
    extern __shared__ char smem[];
    const uint32_t sb = smem_u32(smem);
    const int tid  = threadIdx.x;
    const int wid  = tid >> 5;
    const int lane = tid & 31;

    const int leaf  = blockIdx.x;
    const int cnt   = g_count[leaf];
    const int start = blockIdx.y * BM;
    if (start >= cnt) {
        __syncthreads();
        if (tid == 0) cta_done_and_maybe_reset();
        return;
    }
    const int rows = min(BM, cnt - start);
    const int* list = g_list + leaf * TOKENS + start;

    int* rowTok = (int*)(smem + SM_ROWTOK);
    if (tid < BM) rowTok[tid] = list[min(tid, rows - 1)];
    {
        float* sB1a = (float*)(smem + SM_B1A);
        float* sB1b = (float*)(smem + SM_B1B);
        float* sB2  = (float*)(smem + SM_B2);
        if (tid < FDIM) { sB1a[tid] = b1a[leaf * FDIM + tid]; sB1b[tid] = b1b[leaf * FDIM + tid]; }
        if (tid < DIM)  sB2[tid] = b2[leaf * DIM + tid];
    }
    __syncthreads();

    const int wm = wid & 3;        // m-block: rows 16*wm..+15
    const int wn = wid >> 2;       // n-block 0..3
    const int gid = lane >> 2, tig = lane & 3;
    const int a_row = lane & 15;
    const int a_kad = (lane & 16) >> 1;
    const int b_row = (lane & 7) | ((lane >> 1) & 8);
    const int b_kad = lane & 8;
    const uint32_t arow0 = (uint32_t)((16 * wm + a_row) * 128);

    const int br1[4] = { 32 * wn + b_row, 32 * wn + 16 + b_row,
                         128 + 32 * wn + b_row, 128 + 32 * wn + 16 + b_row };
    const int br2[4] = { 64 * wn + b_row, 64 * wn + 16 + b_row,
                         64 * wn + 32 + b_row, 64 * wn + 48 + b_row };

    // per-thread X source row (512 threads -> 64 rows x 8 segs of 16B)
    const int xq = tid & 7;
    const size_t tokA = (size_t)rowTok[tid >> 3] * DIM;
    const __half* w1base = g_w1t + (size_t)leaf * 256 * DIM;
    const __half* w2base = g_w2t + (size_t)leaf * 512 * FDIM;

    auto issue = [&](int c) {
        const int p = c % 3;
        if (c < 8) {
            const int k0 = c * 64;
            {   // X fp16: 64 rows x 128B, one 16B per thread
                uint32_t so = sw128((uint32_t)((tid >> 3) * 128 + xq * 16));
                cpa16(XB(p) + so, g_x + tokA + k0 + xq * 8);
            }
            const __half* wb = w1base + k0;
            #pragma unroll
            for (int it = 0; it < 4; it++) {           // W1: 256 rows x 128B
                int idx = tid + it * THREADS;
                int wrow = idx >> 3, q = idx & 7;
                uint32_t wo = sw128((uint32_t)(wrow * 128 + q * 16));
                cpa16(WB(p) + wo, wb + (size_t)wrow * DIM + q * 8);
            }
        } else {
            const int idx4 = c - 8, nh = idx4 >> 1, c2 = idx4 & 1;
            const __half* wb = w2base + (size_t)nh * 256 * FDIM + c2 * 64;
            #pragma unroll
            for (int it = 0; it < 4; it++) {
                int idx = tid + it * THREADS;
                int wrow = idx >> 3, q = idx & 7;
                uint32_t wo = sw128((uint32_t)(wrow * 128 + q * 16));
                cpa16(WB(p) + wo, wb + (size_t)wrow * FDIM + q * 8);
            }
        }
        CP_COMMIT();
    };

    issue(0);
    issue(1);

    // ================= phase 1: GEMM1 (chunks 0..7) =================
    {
        float acc[8][4];
        #pragma unroll
        for (int t = 0; t < 8; t++)
            #pragma unroll
            for (int j = 0; j < 4; j++) acc[t][j] = 0.f;

        for (int c = 0; c < 8; c++) {
            const int p = c % 3;
            CP_WAIT(1);                      // chunk c landed
            __syncthreads();                 // all warps past run_fused(c-1)
            issue(c + 2);                    // writes buf (c+2)%3 == (c-1)%3, now free
            run_fused(acc, XB(p), WB(p), arow0, br1, a_kad, b_kad);
        }

        // epilogue1: gate (a tile nt, b tile nt+2) -> H fp16, packed 4B stores
        const float* sB1a = (const float*)(smem + SM_B1A);
        const float* sB1b = (const float*)(smem + SM_B1B);
        const int r0 = 16 * wm + gid;
        #pragma unroll
        for (int nt = 0; nt < 2; nt++) {
            #pragma unroll
            for (int q = 0; q < 2; q++) {
                const int f = 32 * wn + 16 * nt + 8 * q + 2 * tig;
                const float* A = acc[2 * nt + q];
                const float* G = acc[2 * (nt + 2) + q];
                const float ba0 = sB1a[f], ba1 = sB1a[f + 1];
                const float bb0 = sB1b[f], bb1 = sB1b[f + 1];
                const float h00 = (A[0] + ba0) * (G[0] + bb0);
                const float h01 = (A[1] + ba1) * (G[1] + bb1);
                const float h10 = (A[2] + ba0) * (G[2] + bb0);
                const float h11 = (A[3] + ba1) * (G[3] + bb1);
                const int kc = f >> 6, fk = f & 63;
                char* hh = smem + (HB(kc) - sb);
                const uint32_t o0 = sw128((uint32_t)(r0 * 128 + fk * 2));
                const uint32_t o1 = sw128((uint32_t)((r0 + 8) * 128 + fk * 2));
                *(uint32_t*)(hh + o0) = pack_f16x2(__float2half(h00), __float2half(h01));
                *(uint32_t*)(hh + o1) = pack_f16x2(__float2half(h10), __float2half(h11));
            }
        }
    }

    // ================= phase 2: GEMM2 (chunks 8..11) =================
    {
        const float* sB2 = (const float*)(smem + SM_B2);
        int c = 8;
        for (int nh = 0; nh < 2; nh++) {
            float acc2[8][4];
            #pragma unroll
            for (int t = 0; t < 8; t++)
                #pragma unroll
                for (int j = 0; j < 4; j++) acc2[t][j] = 0.f;

            #pragma unroll
            for (int c2 = 0; c2 < 2; c2++, c++) {
                if (c < 11) { CP_WAIT(1); } else { CP_WAIT(0); }
                __syncthreads();             // orders H writes (c==8) and buffer reuse
                if (c + 2 < 12) issue(c + 2);
                run_fused(acc2, HB(c2), WB(c % 3), arow0, br2, a_kad, b_kad);
            }

            const int r0 = 16 * wm + gid;
            #pragma unroll
            for (int t = 0; t < 8; t++) {
                const int col = nh * 256 + 64 * wn + 8 * t + 2 * tig;
                const float c0 = sB2[col], c1 = sB2[col + 1];
                if (r0 < rows) {
                    float2 v = { acc2[t][0] + c0, acc2[t][1] + c1 };
                    *(float2*)(out + (size_t)rowTok[r0] * DIM + col) = v;
                }
                if (r0 + 8 < rows) {
                    float2 v = { acc2[t][2] + c0, acc2[t][3] + c1 };
                    *(float2*)(out + (size_t)rowTok[r0 + 8] * DIM + col) = v;
                }
            }
        }
    }

    __syncthreads();
    if (tid == 0) cta_done_and_maybe_reset();
}

extern "C" void kernel_launch(void* const* d_in, const int* in_sizes, int n_in,
                              void* d_out, int out_size)
{
    const float* x   = (const float*)d_in[0];
    const float* wn0 = (const float*)d_in[2];
    const float* bn0 = (const float*)d_in[3];
    const float* wn1 = (const float*)d_in[4];
    const float* bn1 = (const float*)d_in[5];
    const float* wn2 = (const float*)d_in[6];
    const float* bn2 = (const float*)d_in[7];
    const float* w1a = (const float*)d_in[8];
    const float* b1a = (const float*)d_in[9];
    const float* w1b = (const float*)d_in[10];
    const float* b1b = (const float*)d_in[11];
    const float* w2  = (const float*)d_in[12];
    const float* b2  = (const float*)d_in[13];
    float* out = (float*)d_out;

    static_assert(SMEM_TOTAL <= 227 * 1024, "smem");
    cudaFuncSetAttribute(ffn_kernel, cudaFuncAttributeMaxDynamicSharedMemorySize, SMEM_TOTAL);

    // g_count is zero at entry: zero-initialized at module load, then re-zeroed by
    // ffn_kernel's last CTA on every launch (deterministic across graph replays).
    prep_route_kernel<<<2048, 256>>>(w1a, w1b, w2, x, wn0, bn0, wn1, bn1, wn2, bn2);
    dim3 grid(NLEAF, MAXTILES);
    ffn_kernel<<<grid, THREADS, SMEM_TOTAL>>>(b1a, b1b, b2, out);
}

// round 15
// speedup vs baseline: 1.6564x; 1.0414x over previous
#include <cuda_runtime.h>
#include <cuda_fp16.h>
#include <cstdint>

#define TOKENS   8192
#define DIM      512
#define FDIM     128
#define NLEAF    8
#define BM       64
#define MAXTILES 32
#define THREADS  256
#define TOTAL_CTAS (NLEAF * MAXTILES)

// ---------------- scratch ----------------
__device__ int g_count[NLEAF];          // zero-init at load; re-zeroed by ffn's last CTA
__device__ int g_done;                  // ffn completion counter (self-resetting)
__device__ int g_list[NLEAF * TOKENS];
__device__ __half g_x[TOKENS * DIM];    // fp16 activations
// W1 transposed fp16: [leaf][n=256][k=512]; n<128 -> w1a col n, n>=128 -> w1b col n-128
__device__ __half g_w1t[NLEAF * 256 * 512];
// W2 transposed fp16: [leaf][n=512][k=128]
__device__ __half g_w2t[NLEAF * 512 * 128];

__device__ __forceinline__ uint32_t smem_u32(const void* p) {
    uint32_t a;
    asm("{ .reg .u64 t; cvta.to.shared.u64 t, %1; cvt.u32.u64 %0, t; }" : "=r"(a) : "l"(p));
    return a;
}
__device__ __forceinline__ uint32_t sw128(uint32_t off) { return off ^ ((off >> 3) & 0x70); }

__device__ __forceinline__ uint32_t pack_f16x2(__half a, __half b) {
    union { __half h[2]; uint32_t u; } t;
    t.h[0] = a; t.h[1] = b;
    return t.u;
}

__device__ __forceinline__ void cpa16(uint32_t dst, const void* src) {
    asm volatile("cp.async.cg.shared.global [%0], [%1], 16;" :: "r"(dst), "l"(src) : "memory");
}
#define CP_COMMIT() asm volatile("cp.async.commit_group;" ::: "memory")
#define CP_WAIT(n)  asm volatile("cp.async.wait_group %0;" :: "n"(n) : "memory")

#define LDSM4(r, a)                                                                   \
    asm volatile("ldmatrix.sync.aligned.m8n8.x4.shared.b16 {%0,%1,%2,%3}, [%4];"     \
        : "=r"((r)[0]), "=r"((r)[1]), "=r"((r)[2]), "=r"((r)[3]) : "r"(a))

__device__ __forceinline__ void mma_f16(float* d, const uint32_t* a, uint32_t b0, uint32_t b1) {
    asm volatile(
        "mma.sync.aligned.m16n8k16.row.col.f32.f16.f16.f32 "
        "{%0,%1,%2,%3},{%4,%5,%6,%7},{%8,%9},{%0,%1,%2,%3};"
        : "+f"(d[0]), "+f"(d[1]), "+f"(d[2]), "+f"(d[3])
        : "r"(a[0]), "r"(a[1]), "r"(a[2]), "r"(a[3]), "r"(b0), "r"(b1));
}

// Single-pass fp16 chunk, warp tile M16xN128: per kof -> 9 LDSM4, 16 HMMA.
__device__ __forceinline__ void run_fused8(
    float acc[16][4], uint32_t A, uint32_t B,
    uint32_t arow0, const int br[8], int a_kad, int b_kad)
{
    #pragma unroll
    for (int kof = 0; kof < 64; kof += 16) {
        uint32_t af[4], bf[8][4];
        LDSM4(af, A + sw128(arow0 + (kof + a_kad) * 2));
        #pragma unroll
        for (int nt = 0; nt < 8; nt++)
            LDSM4(bf[nt], B + sw128((uint32_t)(br[nt] * 128 + (kof + b_kad) * 2)));
        #pragma unroll
        for (int nt = 0; nt < 8; nt++) {
            mma_f16(acc[2 * nt],     af, bf[nt][0], bf[nt][1]);
            mma_f16(acc[2 * nt + 1], af, bf[nt][2], bf[nt][3]);
        }
    }
}

__device__ __forceinline__ float warp_sum(float v) {
    #pragma unroll
    for (int o = 16; o > 0; o >>= 1) v += __shfl_xor_sync(0xFFFFFFFFu, v, o);
    return v;
}

// ---------------- fused prep (W transpose->fp16) + routing + X fp16 ----------------
// blocks [0,512): W1; [512,1024): W2; [1024,2048): route (8 tokens per block). 256 threads.
__global__ void prep_route_kernel(
    const float* __restrict__ w1a, const float* __restrict__ w1b, const float* __restrict__ w2,
    const float* __restrict__ x,
    const float* __restrict__ wn0, const float* __restrict__ bn0,
    const float* __restrict__ wn1, const float* __restrict__ bn1,
    const float* __restrict__ wn2, const float* __restrict__ bn2)
{
    const int bid = blockIdx.x;
    const int tid = threadIdx.x;

    if (bid < 512) {        // ---- W1: leaf/kt/ft ----
        const int leaf = bid >> 6, rem = bid & 63, kt = rem >> 2, ft = rem & 3;
        __shared__ float ta[32][33], tb[32][33];
        {
            int r = tid >> 3, cq = tid & 7;
            size_t src = ((size_t)leaf * 512 + kt * 32 + r) * 128 + ft * 32 + cq * 4;
            float4 va = *(const float4*)(w1a + src);
            float4 vb = *(const float4*)(w1b + src);
            ta[r][cq*4+0]=va.x; ta[r][cq*4+1]=va.y; ta[r][cq*4+2]=va.z; ta[r][cq*4+3]=va.w;
            tb[r][cq*4+0]=vb.x; tb[r][cq*4+1]=vb.y; tb[r][cq*4+2]=vb.z; tb[r][cq*4+3]=vb.w;
        }
        __syncthreads();
        {
            int n = tid >> 2, kq = tid & 3;
            int side = n >> 5, fl = n & 31;
            union { __half h[8]; uint4 u; } h8;
            #pragma unroll
            for (int j = 0; j < 8; j++) {
                float v = side ? tb[kq * 8 + j][fl] : ta[kq * 8 + j][fl];
                h8.h[j] = __float2half(v);
            }
            int orow = side ? (128 + ft * 32 + fl) : (ft * 32 + fl);
            size_t off = ((size_t)leaf * 256 + orow) * 512 + kt * 32 + kq * 8;
            *(uint4*)(g_w1t + off) = h8.u;
        }
    } else if (bid < 1024) {    // ---- W2: leaf/dt/kt ----
        const int b2i = bid - 512;
        const int leaf = b2i >> 6, rem = b2i & 63, dt = rem >> 2, kt = rem & 3;
        __shared__ float t[32][33];
        {
            int r = tid >> 3, cq = tid & 7;
            size_t src = ((size_t)leaf * 128 + kt * 32 + r) * 512 + dt * 32 + cq * 4;
            float4 v = *(const float4*)(w2 + src);
            t[r][cq*4+0]=v.x; t[r][cq*4+1]=v.y; t[r][cq*4+2]=v.z; t[r][cq*4+3]=v.w;
        }
        __syncthreads();
        {
            int n = tid >> 3, kq = tid & 7;
            union { __half h[4]; uint2 u; } h4;
            #pragma unroll
            for (int j = 0; j < 4; j++) h4.h[j] = __float2half(t[kq * 4 + j][n]);
            size_t orow = ((size_t)leaf * 512 + dt * 32 + n) * 128 + kt * 32 + kq * 4;
            *(uint2*)(g_w2t + orow) = h4.u;
        }
    } else {                // ---- route: one warp per token, single-pass 7 logits ----
        const int gwarp = (bid - 1024) * 8 + (tid >> 5);
        const int lane  = tid & 31;

        const float4* xr4 = (const float4*)(x + (size_t)gwarp * DIM);
        float4 xv[4];
        #pragma unroll
        for (int i = 0; i < 4; i++) xv[i] = xr4[lane + i * 32];

        {   // X fp16 write (reused by ffn via cp.async)
            __half* xh = g_x + (size_t)gwarp * DIM;
            #pragma unroll
            for (int i = 0; i < 4; i++) {
                union { __half h[4]; uint2 u; } h4;
                h4.h[0] = __float2half(xv[i].x);
                h4.h[1] = __float2half(xv[i].y);
                h4.h[2] = __float2half(xv[i].z);
                h4.h[3] = __float2half(xv[i].w);
                *(uint2*)(xh + (lane + i * 32) * 4) = h4.u;
            }
        }

        // all 7 node logits in one pass (s0; s1,s2 depth1; s3..s6 depth2)
        float s[7];
        #pragma unroll
        for (int j = 0; j < 7; j++) s[j] = 0.f;
        #pragma unroll
        for (int i = 0; i < 4; i++) {
            const int k4 = (lane + i * 32) * 4;
            const float4 v = xv[i];
            float4 w0 = *(const float4*)(wn0 + k4);
            s[0] += v.x * w0.x + v.y * w0.y + v.z * w0.z + v.w * w0.w;
            float4 wA = *(const float4*)(wn1 + k4 * 2);       // k4,k4+1 (cols 0,1)
            float4 wB = *(const float4*)(wn1 + k4 * 2 + 4);   // k4+2,k4+3
            s[1] += v.x * wA.x + v.y * wA.z + v.z * wB.x + v.w * wB.z;
            s[2] += v.x * wA.y + v.y * wA.w + v.z * wB.y + v.w * wB.w;
            float4 w20 = *(const float4*)(wn2 + k4 * 4);
            float4 w21 = *(const float4*)(wn2 + k4 * 4 + 4);
            float4 w22 = *(const float4*)(wn2 + k4 * 4 + 8);
            float4 w23 = *(const float4*)(wn2 + k4 * 4 + 12);
            s[3] += v.x * w20.x + v.y * w21.x + v.z * w22.x + v.w * w23.x;
            s[4] += v.x * w20.y + v.y * w21.y + v.z * w22.y + v.w * w23.y;
            s[5] += v.x * w20.z + v.y * w21.z + v.z * w22.z + v.w * w23.z;
            s[6] += v.x * w20.w + v.y * w21.w + v.z * w22.w + v.w * w23.w;
        }
        #pragma unroll
        for (int j = 0; j < 7; j++) s[j] = warp_sum(s[j]);   // independent: pipeline

        int node = ((s[0] + bn0[0]) > 0.f) ? 0 : 1;
        node = node * 2 + (((s[1 + node] + bn1[node]) > 0.f) ? 0 : 1);
        int leaf = node * 2 + (((s[3 + node] + bn2[node]) > 0.f) ? 0 : 1);

        if (lane == 0) {
            int pos = atomicAdd(&g_count[leaf], 1);
            g_list[leaf * TOKENS + pos] = gwarp;
        }
    }
}

// ---------------- SMEM layout: 2-stage pipeline, fits 2 CTAs/SM ----------------
#define SM_ROWTOK  0
#define SM_B1A     256
#define SM_B1B     768
#define SM_B2      1280                     // ends 3328
#define SM_X       4096                     // 2 buf x 8KB = 16KB -> ends 20480
#define SM_W       20480                    // 2 buf x 32KB = 64KB -> ends 86016
#define SM_H       86016                    // 2 x 8KB -> ends 102400
#define SMEM_TOTAL 102400

#define XB(p)  (sb + SM_X + (p) * 8192)
#define WB(p)  (sb + SM_W + (p) * 32768)
#define HB(k)  (sb + SM_H + (k) * 8192)

__device__ __forceinline__ void cta_done_and_maybe_reset() {
    int old = atomicAdd(&g_done, 1);
    if (old == TOTAL_CTAS - 1) {
        #pragma unroll
        for (int i = 0; i < NLEAF; i++) g_count[i] = 0;
        __threadfence();
        g_done = 0;
    }
}

// ---------------- fused leaf FFN: 8 warps M16xN128, 2 CTAs/SM ----------------
__global__ void __launch_bounds__(THREADS, 2)
ffn_kernel(const float* __restrict__ b1a, const float* __restrict__ b1b,
           const float* __restrict__ b2,  float* __restrict__ out)
{
    extern __shared__ char smem[];
    const uint32_t sb = smem_u32(smem);
    const int tid  = threadIdx.x;
    const int wid  = tid >> 5;
    const int lane = tid & 31;

    const int leaf  = blockIdx.x;
    const int cnt   = g_count[leaf];
    const int start = blockIdx.y * BM;
    if (start >= cnt) {
        __syncthreads();
        if (tid == 0) cta_done_and_maybe_reset();
        return;
    }
    const int rows = min(BM, cnt - start);
    const int* list = g_list + leaf * TOKENS + start;

    int* rowTok = (int*)(smem + SM_ROWTOK);
    if (tid < BM) rowTok[tid] = list[min(tid, rows - 1)];
    {
        float* sB1a = (float*)(smem + SM_B1A);
        float* sB1b = (float*)(smem + SM_B1B);
        float* sB2  = (float*)(smem + SM_B2);
        if (tid < FDIM) { sB1a[tid] = b1a[leaf * FDIM + tid]; sB1b[tid] = b1b[leaf * FDIM + tid]; }
        for (int i = tid; i < DIM; i += THREADS) sB2[i] = b2[leaf * DIM + i];
    }
    __syncthreads();

    const int wm = wid & 3;        // m-block: rows 16*wm..+15
    const int wn = wid >> 2;       // n-block 0..1 (128 cols each)
    const int gid = lane >> 2, tig = lane & 3;
    const int a_row = lane & 15;
    const int a_kad = (lane & 16) >> 1;
    const int b_row = (lane & 7) | ((lane >> 1) & 8);
    const int b_kad = lane & 8;
    const uint32_t arow0 = (uint32_t)((16 * wm + a_row) * 128);

    // GEMM1: warp covers a-cols [64wn,64wn+64) (nt 0..3) + b-cols 128+same (nt 4..7)
    int br1[8], br2[8];
    #pragma unroll
    for (int t = 0; t < 4; t++) {
        br1[t]     = 64 * wn + 16 * t + b_row;
        br1[t + 4] = 128 + 64 * wn + 16 * t + b_row;
    }
    #pragma unroll
    for (int t = 0; t < 8; t++) br2[t] = 128 * wn + 16 * t + b_row;

    // loaders (256 threads)
    const int xq = tid & 7;
    const size_t tokA = (size_t)rowTok[tid >> 3] * DIM;        // rows 0..31
    const size_t tokB = (size_t)rowTok[(tid >> 3) + 32] * DIM; // rows 32..63
    const __half* w1base = g_w1t + (size_t)leaf * 256 * DIM;
    const __half* w2base = g_w2t + (size_t)leaf * 512 * FDIM;

    auto issue = [&](int c) {
        const int p = c & 1;
        if (c < 8) {
            const int k0 = c * 64;
            {   // X fp16: 64 rows x 128B, two rows per thread
                const int ra = tid >> 3;
                cpa16(XB(p) + sw128((uint32_t)(ra * 128 + xq * 16)),        g_x + tokA + k0 + xq * 8);
                cpa16(XB(p) + sw128((uint32_t)((ra + 32) * 128 + xq * 16)), g_x + tokB + k0 + xq * 8);
            }
            const __half* wb = w1base + k0;
            #pragma unroll
            for (int it = 0; it < 8; it++) {           // W1: 256 rows x 128B
                int idx = tid + it * THREADS;
                int wrow = idx >> 3, q = idx & 7;
                uint32_t wo = sw128((uint32_t)(wrow * 128 + q * 16));
                cpa16(WB(p) + wo, wb + (size_t)wrow * DIM + q * 8);
            }
        } else {
            const int idx4 = c - 8, nh = idx4 >> 1, c2 = idx4 & 1;
            const __half* wb = w2base + (size_t)nh * 256 * FDIM + c2 * 64;
            #pragma unroll
            for (int it = 0; it < 8; it++) {
                int idx = tid + it * THREADS;
                int wrow = idx >> 3, q = idx & 7;
                uint32_t wo = sw128((uint32_t)(wrow * 128 + q * 16));
                cpa16(WB(p) + wo, wb + (size_t)wrow * FDIM + q * 8);
            }
        }
        CP_COMMIT();
    };

    issue(0);

    // ================= phase 1: GEMM1 (chunks 0..7) =================
    {
        float acc[16][4];
        #pragma unroll
        for (int t = 0; t < 16; t++)
            #pragma unroll
            for (int j = 0; j < 4; j++) acc[t][j] = 0.f;

        for (int c = 0; c < 8; c++) {
            const int p = c & 1;
            CP_WAIT(0);                      // chunk c landed
            __syncthreads();                 // all warps past run_fused(c-1)
            issue(c + 1);                    // other buffer, free after barrier
            run_fused8(acc, XB(p), WB(p), arow0, br1, a_kad, b_kad);
        }

        // epilogue1: gate (a tile nt, b tile nt+4) -> H fp16, packed 4B stores
        const float* sB1a = (const float*)(smem + SM_B1A);
        const float* sB1b = (const float*)(smem + SM_B1B);
        const int r0 = 16 * wm + gid;
        #pragma unroll
        for (int nt = 0; nt < 4; nt++) {
            #pragma unroll
            for (int q = 0; q < 2; q++) {
                const int f = 64 * wn + 16 * nt + 8 * q + 2 * tig;
                const float* A = acc[2 * nt + q];
                const float* G = acc[8 + 2 * nt + q];
                const float ba0 = sB1a[f], ba1 = sB1a[f + 1];
                const float bb0 = sB1b[f], bb1 = sB1b[f + 1];
                const float h00 = (A[0] + ba0) * (G[0] + bb0);
                const float h01 = (A[1] + ba1) * (G[1] + bb1);
                const float h10 = (A[2] + ba0) * (G[2] + bb0);
                const float h11 = (A[3] + ba1) * (G[3] + bb1);
                const int kc = f >> 6, fk = f & 63;
                char* hh = smem + (HB(kc) - sb);
                const uint32_t o0 = sw128((uint32_t)(r0 * 128 + fk * 2));
                const uint32_t o1 = sw128((uint32_t)((r0 + 8) * 128 + fk * 2));
                *(uint32_t*)(hh + o0) = pack_f16x2(__float2half(h00), __float2half(h01));
                *(uint32_t*)(hh + o1) = pack_f16x2(__float2half(h10), __float2half(h11));
            }
        }
    }

    // ================= phase 2: GEMM2 (chunks 8..11) =================
    {
        const float* sB2 = (const float*)(smem + SM_B2);
        int c = 8;
        for (int nh = 0; nh < 2; nh++) {
            float acc2[16][4];
            #pragma unroll
            for (int t = 0; t < 16; t++)
                #pragma unroll
                for (int j = 0; j < 4; j++) acc2[t][j] = 0.f;

            #pragma unroll
            for (int c2 = 0; c2 < 2; c2++, c++) {
                CP_WAIT(0);
                __syncthreads();             // orders H writes (c==8) and buffer reuse
                if (c + 1 < 12) issue(c + 1);
                run_fused8(acc2, HB(c2), WB(c & 1), arow0, br2, a_kad, b_kad);
            }

            const int r0 = 16 * wm + gid;
            #pragma unroll
            for (int t = 0; t < 16; t++) {
                const int col = nh * 256 + 128 * wn + 8 * t + 2 * tig;
                const float c0 = sB2[col], c1 = sB2[col + 1];
                if (r0 < rows) {
                    float2 v = { acc2[t][0] + c0, acc2[t][1] + c1 };
                    *(float2*)(out + (size_t)rowTok[r0] * DIM + col) = v;
                }
                if (r0 + 8 < rows) {
                    float2 v = { acc2[t][2] + c0, acc2[t][3] + c1 };
                    *(float2*)(out + (size_t)rowTok[r0 + 8] * DIM + col) = v;
                }
            }
        }
    }

    __syncthreads();
    if (tid == 0) cta_done_and_maybe_reset();
}

extern "C" void kernel_launch(void* const* d_in, const int* in_sizes, int n_in,
                              void* d_out, int out_size)
{
    const float* x   = (const float*)d_in[0];
    const float* wn0 = (const float*)d_in[2];
    const float* bn0 = (const float*)d_in[3];
    const float* wn1 = (const float*)d_in[4];
    const float* bn1 = (const float*)d_in[5];
    const float* wn2 = (const float*)d_in[6];
    const float* bn2 = (const float*)d_in[7];
    const float* w1a = (const float*)d_in[8];
    const float* b1a = (const float*)d_in[9];
    const float* w1b = (const float*)d_in[10];
    const float* b1b = (const float*)d_in[11];
    const float* w2  = (const float*)d_in[12];
    const float* b2  = (const float*)d_in[13];
    float* out = (float*)d_out;

    static_assert(SMEM_TOTAL <= 113 * 1024, "smem for 2 CTAs/SM");
    cudaFuncSetAttribute(ffn_kernel, cudaFuncAttributeMaxDynamicSharedMemorySize, SMEM_TOTAL);

    // g_count is zero at entry: zero-initialized at module load, then re-zeroed by
    // ffn_kernel's last CTA on every launch (deterministic across graph replays).
    prep_route_kernel<<<2048, 256>>>(w1a, w1b, w2, x, wn0, bn0, wn1, bn1, wn2, bn2);
    dim3 grid(NLEAF, MAXTILES);
    ffn_kernel<<<grid, THREADS, SMEM_TOTAL>>>(b1a, b1b, b2, out);
}

// round 16
// speedup vs baseline: 1.7338x; 1.0468x over previous
#include <cuda_runtime.h>
#include <cuda_fp16.h>
#include <cstdint>

#define TOKENS   8192
#define DIM      512
#define FDIM     128
#define NLEAF    8
#define BM       64
#define MAXTILES 32
#define THREADS  512
#define TOTAL_CTAS (NLEAF * MAXTILES)

// ---------------- scratch ----------------
__device__ int g_count[NLEAF];          // zero-init at load; re-zeroed by ffn's last CTA
__device__ int g_done;                  // ffn completion counter (self-resetting)
__device__ int g_list[NLEAF * TOKENS];
__device__ __half g_x[TOKENS * DIM];    // fp16 activations
// W1 transposed fp16: [leaf][n=256][k=512]; n<128 -> w1a col n, n>=128 -> w1b col n-128
__device__ __half g_w1t[NLEAF * 256 * 512];
// W2 transposed fp16: [leaf][n=512][k=128]
__device__ __half g_w2t[NLEAF * 512 * 128];

__device__ __forceinline__ uint32_t smem_u32(const void* p) {
    uint32_t a;
    asm("{ .reg .u64 t; cvta.to.shared.u64 t, %1; cvt.u32.u64 %0, t; }" : "=r"(a) : "l"(p));
    return a;
}
__device__ __forceinline__ uint32_t sw128(uint32_t off) { return off ^ ((off >> 3) & 0x70); }

__device__ __forceinline__ uint32_t pack_f16x2(__half a, __half b) {
    union { __half h[2]; uint32_t u; } t;
    t.h[0] = a; t.h[1] = b;
    return t.u;
}

__device__ __forceinline__ void cpa16(uint32_t dst, const void* src) {
    asm volatile("cp.async.cg.shared.global [%0], [%1], 16;" :: "r"(dst), "l"(src) : "memory");
}
#define CP_COMMIT() asm volatile("cp.async.commit_group;" ::: "memory")
#define CP_WAIT(n)  asm volatile("cp.async.wait_group %0;" :: "n"(n) : "memory")

#define LDSM4(r, a)                                                                   \
    asm volatile("ldmatrix.sync.aligned.m8n8.x4.shared.b16 {%0,%1,%2,%3}, [%4];"     \
        : "=r"((r)[0]), "=r"((r)[1]), "=r"((r)[2]), "=r"((r)[3]) : "r"(a))

__device__ __forceinline__ void mma_f16(float* d, const uint32_t* a, uint32_t b0, uint32_t b1) {
    asm volatile(
        "mma.sync.aligned.m16n8k16.row.col.f32.f16.f16.f32 "
        "{%0,%1,%2,%3},{%4,%5,%6,%7},{%8,%9},{%0,%1,%2,%3};"
        : "+f"(d[0]), "+f"(d[1]), "+f"(d[2]), "+f"(d[3])
        : "r"(a[0]), "r"(a[1]), "r"(a[2]), "r"(a[3]), "r"(b0), "r"(b1));
}

// Single-pass fp16 chunk, warp tile M16xN64: per kof -> 5 LDSM4, 8 HMMA.
__device__ __forceinline__ void run_fused(
    float acc[8][4], uint32_t A, uint32_t B,
    uint32_t arow0, const int br[4], int a_kad, int b_kad)
{
    #pragma unroll
    for (int kof = 0; kof < 64; kof += 16) {
        uint32_t af[4], bf[4][4];
        LDSM4(af, A + sw128(arow0 + (kof + a_kad) * 2));
        #pragma unroll
        for (int nt = 0; nt < 4; nt++)
            LDSM4(bf[nt], B + sw128((uint32_t)(br[nt] * 128 + (kof + b_kad) * 2)));
        #pragma unroll
        for (int nt = 0; nt < 4; nt++) {
            mma_f16(acc[2 * nt],     af, bf[nt][0], bf[nt][1]);
            mma_f16(acc[2 * nt + 1], af, bf[nt][2], bf[nt][3]);
        }
    }
}

__device__ __forceinline__ float warp_sum(float v) {
    #pragma unroll
    for (int o = 16; o > 0; o >>= 1) v += __shfl_xor_sync(0xFFFFFFFFu, v, o);
    return v;
}

// ---------------- fused prep (W transpose->fp16) + routing + X fp16 ----------------
// blocks [0,512): W1; [512,1024): W2; [1024,2048): route (8 tokens per block). 256 threads.
__global__ void prep_route_kernel(
    const float* __restrict__ w1a, const float* __restrict__ w1b, const float* __restrict__ w2,
    const float* __restrict__ x,
    const float* __restrict__ wn0, const float* __restrict__ bn0,
    const float* __restrict__ wn1, const float* __restrict__ bn1,
    const float* __restrict__ wn2, const float* __restrict__ bn2)
{
    const int bid = blockIdx.x;
    const int tid = threadIdx.x;

    if (bid < 512) {        // ---- W1: leaf/kt/ft ----
        const int leaf = bid >> 6, rem = bid & 63, kt = rem >> 2, ft = rem & 3;
        __shared__ float ta[32][33], tb[32][33];
        {
            int r = tid >> 3, cq = tid & 7;
            size_t src = ((size_t)leaf * 512 + kt * 32 + r) * 128 + ft * 32 + cq * 4;
            float4 va = *(const float4*)(w1a + src);
            float4 vb = *(const float4*)(w1b + src);
            ta[r][cq*4+0]=va.x; ta[r][cq*4+1]=va.y; ta[r][cq*4+2]=va.z; ta[r][cq*4+3]=va.w;
            tb[r][cq*4+0]=vb.x; tb[r][cq*4+1]=vb.y; tb[r][cq*4+2]=vb.z; tb[r][cq*4+3]=vb.w;
        }
        __syncthreads();
        {
            int n = tid >> 2, kq = tid & 3;
            int side = n >> 5, fl = n & 31;
            union { __half h[8]; uint4 u; } h8;
            #pragma unroll
            for (int j = 0; j < 8; j++) {
                float v = side ? tb[kq * 8 + j][fl] : ta[kq * 8 + j][fl];
                h8.h[j] = __float2half(v);
            }
            int orow = side ? (128 + ft * 32 + fl) : (ft * 32 + fl);
            size_t off = ((size_t)leaf * 256 + orow) * 512 + kt * 32 + kq * 8;
            *(uint4*)(g_w1t + off) = h8.u;
        }
    } else if (bid < 1024) {    // ---- W2: leaf/dt/kt ----
        const int b2i = bid - 512;
        const int leaf = b2i >> 6, rem = b2i & 63, dt = rem >> 2, kt = rem & 3;
        __shared__ float t[32][33];
        {
            int r = tid >> 3, cq = tid & 7;
            size_t src = ((size_t)leaf * 128 + kt * 32 + r) * 512 + dt * 32 + cq * 4;
            float4 v = *(const float4*)(w2 + src);
            t[r][cq*4+0]=v.x; t[r][cq*4+1]=v.y; t[r][cq*4+2]=v.z; t[r][cq*4+3]=v.w;
        }
        __syncthreads();
        {
            int n = tid >> 3, kq = tid & 7;
            union { __half h[4]; uint2 u; } h4;
            #pragma unroll
            for (int j = 0; j < 4; j++) h4.h[j] = __float2half(t[kq * 4 + j][n]);
            size_t orow = ((size_t)leaf * 512 + dt * 32 + n) * 128 + kt * 32 + kq * 4;
            *(uint2*)(g_w2t + orow) = h4.u;
        }
    } else {                // ---- route: one warp per token, single-pass 7 logits ----
        const int gwarp = (bid - 1024) * 8 + (tid >> 5);
        const int lane  = tid & 31;

        const float4* xr4 = (const float4*)(x + (size_t)gwarp * DIM);
        float4 xv[4];
        #pragma unroll
        for (int i = 0; i < 4; i++) xv[i] = xr4[lane + i * 32];

        {   // X fp16 write (reused by ffn via cp.async)
            __half* xh = g_x + (size_t)gwarp * DIM;
            #pragma unroll
            for (int i = 0; i < 4; i++) {
                union { __half h[4]; uint2 u; } h4;
                h4.h[0] = __float2half(xv[i].x);
                h4.h[1] = __float2half(xv[i].y);
                h4.h[2] = __float2half(xv[i].z);
                h4.h[3] = __float2half(xv[i].w);
                *(uint2*)(xh + (lane + i * 32) * 4) = h4.u;
            }
        }

        // all 7 node logits in one pass (s0; s1,s2 depth1; s3..s6 depth2)
        float s[7];
        #pragma unroll
        for (int j = 0; j < 7; j++) s[j] = 0.f;
        #pragma unroll
        for (int i = 0; i < 4; i++) {
            const int k4 = (lane + i * 32) * 4;
            const float4 v = xv[i];
            float4 w0 = *(const float4*)(wn0 + k4);
            s[0] += v.x * w0.x + v.y * w0.y + v.z * w0.z + v.w * w0.w;
            float4 wA = *(const float4*)(wn1 + k4 * 2);       // k4,k4+1 (cols 0,1)
            float4 wB = *(const float4*)(wn1 + k4 * 2 + 4);   // k4+2,k4+3
            s[1] += v.x * wA.x + v.y * wA.z + v.z * wB.x + v.w * wB.z;
            s[2] += v.x * wA.y + v.y * wA.w + v.z * wB.y + v.w * wB.w;
            float4 w20 = *(const float4*)(wn2 + k4 * 4);
            float4 w21 = *(const float4*)(wn2 + k4 * 4 + 4);
            float4 w22 = *(const float4*)(wn2 + k4 * 4 + 8);
            float4 w23 = *(const float4*)(wn2 + k4 * 4 + 12);
            s[3] += v.x * w20.x + v.y * w21.x + v.z * w22.x + v.w * w23.x;
            s[4] += v.x * w20.y + v.y * w21.y + v.z * w22.y + v.w * w23.y;
            s[5] += v.x * w20.z + v.y * w21.z + v.z * w22.z + v.w * w23.z;
            s[6] += v.x * w20.w + v.y * w21.w + v.z * w22.w + v.w * w23.w;
        }
        #pragma unroll
        for (int j = 0; j < 7; j++) s[j] = warp_sum(s[j]);   // independent: pipeline

        int node = ((s[0] + bn0[0]) > 0.f) ? 0 : 1;
        node = node * 2 + (((s[1 + node] + bn1[node]) > 0.f) ? 0 : 1);
        int leaf = node * 2 + (((s[3 + node] + bn2[node]) > 0.f) ? 0 : 1);

        if (lane == 0) {
            int pos = atomicAdd(&g_count[leaf], 1);
            g_list[leaf * TOKENS + pos] = gwarp;
        }
    }
}

// ---------------- SMEM layout: 3-stage pipeline (round-14 ffn) ----------------
#define SM_ROWTOK  0
#define SM_B1A     256
#define SM_B1B     768
#define SM_B2      1280                     // 2KB -> ends 3328
#define SM_X       4096                     // 3 buf x 8KB = 24KB -> ends 28672
#define SM_W       28672                    // 3 buf x 32KB = 96KB -> ends 126976
#define SM_H       126976                   // 2 x 8KB = 16KB -> ends 143360
#define SMEM_TOTAL 143360

#define XB(p)  (sb + SM_X + (p) * 8192)
#define WB(p)  (sb + SM_W + (p) * 32768)
#define HB(k)  (sb + SM_H + (k) * 8192)

__device__ __forceinline__ void cta_done_and_maybe_reset() {
    int old = atomicAdd(&g_done, 1);
    if (old == TOTAL_CTAS - 1) {
        #pragma unroll
        for (int i = 0; i < NLEAF; i++) g_count[i] = 0;
        __threadfence();
        g_done = 0;
    }
}

// ---------------- fused leaf FFN: single-pass fp16, 16 warps, M16xN64 ----------------
__global__ void __launch_bounds__(THREADS, 1)
ffn_kernel(const float* __restrict__ b1a, const float* __restrict__ b1b,
           const float* __restrict__ b2,  float* __restrict__ out)
{
    extern __shared__ char smem[];
    const uint32_t sb = smem_u32(smem);
    const int tid  = threadIdx.x;
    const int wid  = tid >> 5;
    const int lane = tid & 31;

    const int leaf  = blockIdx.x;
    const int cnt   = g_count[leaf];
    const int start = blockIdx.y * BM;
    if (start >= cnt) {
        __syncthreads();
        if (tid == 0) cta_done_and_maybe_reset();
        return;
    }
    const int rows = min(BM, cnt - start);
    const int* list = g_list + leaf * TOKENS + start;

    int* rowTok = (int*)(smem + SM_ROWTOK);
    if (tid < BM) rowTok[tid] = list[min(tid, rows - 1)];
    {
        float* sB1a = (float*)(smem + SM_B1A);
        float* sB1b = (float*)(smem + SM_B1B);
        float* sB2  = (float*)(smem + SM_B2);
        if (tid < FDIM) { sB1a[tid] = b1a[leaf * FDIM + tid]; sB1b[tid] = b1b[leaf * FDIM + tid]; }
        if (tid < DIM)  sB2[tid] = b2[leaf * DIM + tid];
    }
    __syncthreads();

    const int wm = wid & 3;        // m-block: rows 16*wm..+15
    const int wn = wid >> 2;       // n-block 0..3
    const int gid = lane >> 2, tig = lane & 3;
    const int a_row = lane & 15;
    const int a_kad = (lane & 16) >> 1;
    const int b_row = (lane & 7) | ((lane >> 1) & 8);
    const int b_kad = lane & 8;
    const uint32_t arow0 = (uint32_t)((16 * wm + a_row) * 128);

    const int br1[4] = { 32 * wn + b_row, 32 * wn + 16 + b_row,
                         128 + 32 * wn + b_row, 128 + 32 * wn + 16 + b_row };
    const int br2[4] = { 64 * wn + b_row, 64 * wn + 16 + b_row,
                         64 * wn + 32 + b_row, 64 * wn + 48 + b_row };

    // per-thread X source row (512 threads -> 64 rows x 8 segs of 16B)
    const int xq = tid & 7;
    const size_t tokA = (size_t)rowTok[tid >> 3] * DIM;
    const __half* w1base = g_w1t + (size_t)leaf * 256 * DIM;
    const __half* w2base = g_w2t + (size_t)leaf * 512 * FDIM;

    auto issue = [&](int c) {
        const int p = c % 3;
        if (c < 8) {
            const int k0 = c * 64;
            {   // X fp16: 64 rows x 128B, one 16B per thread
                uint32_t so = sw128((uint32_t)((tid >> 3) * 128 + xq * 16));
                cpa16(XB(p) + so, g_x + tokA + k0 + xq * 8);
            }
            const __half* wb = w1base + k0;
            #pragma unroll
            for (int it = 0; it < 4; it++) {           // W1: 256 rows x 128B
                int idx = tid + it * THREADS;
                int wrow = idx >> 3, q = idx & 7;
                uint32_t wo = sw128((uint32_t)(wrow * 128 + q * 16));
                cpa16(WB(p) + wo, wb + (size_t)wrow * DIM + q * 8);
            }
        } else {
            const int idx4 = c - 8, nh = idx4 >> 1, c2 = idx4 & 1;
            const __half* wb = w2base + (size_t)nh * 256 * FDIM + c2 * 64;
            #pragma unroll
            for (int it = 0; it < 4; it++) {
                int idx = tid + it * THREADS;
                int wrow = idx >> 3, q = idx & 7;
                uint32_t wo = sw128((uint32_t)(wrow * 128 + q * 16));
                cpa16(WB(p) + wo, wb + (size_t)wrow * FDIM + q * 8);
            }
        }
        CP_COMMIT();
    };

    issue(0);
    issue(1);

    // ================= phase 1: GEMM1 (chunks 0..7) =================
    {
        float acc[8][4];
        #pragma unroll
        for (int t = 0; t < 8; t++)
            #pragma unroll
            for (int j = 0; j < 4; j++) acc[t][j] = 0.f;

        for (int c = 0; c < 8; c++) {
            const int p = c % 3;
            CP_WAIT(1);                      // chunk c landed
            __syncthreads();                 // all warps past run_fused(c-1)
            issue(c + 2);                    // writes buf (c+2)%3 == (c-1)%3, now free
            run_fused(acc, XB(p), WB(p), arow0, br1, a_kad, b_kad);
        }

        // epilogue1: gate (a tile nt, b tile nt+2) -> H fp16, packed 4B stores
        const float* sB1a = (const float*)(smem + SM_B1A);
        const float* sB1b = (const float*)(smem + SM_B1B);
        const int r0 = 16 * wm + gid;
        #pragma unroll
        for (int nt = 0; nt < 2; nt++) {
            #pragma unroll
            for (int q = 0; q < 2; q++) {
                const int f = 32 * wn + 16 * nt + 8 * q + 2 * tig;
                const float* A = acc[2 * nt + q];
                const float* G = acc[2 * (nt + 2) + q];
                const float ba0 = sB1a[f], ba1 = sB1a[f + 1];
                const float bb0 = sB1b[f], bb1 = sB1b[f + 1];
                const float h00 = (A[0] + ba0) * (G[0] + bb0);
                const float h01 = (A[1] + ba1) * (G[1] + bb1);
                const float h10 = (A[2] + ba0) * (G[2] + bb0);
                const float h11 = (A[3] + ba1) * (G[3] + bb1);
                const int kc = f >> 6, fk = f & 63;
                char* hh = smem + (HB(kc) - sb);
                const uint32_t o0 = sw128((uint32_t)(r0 * 128 + fk * 2));
                const uint32_t o1 = sw128((uint32_t)((r0 + 8) * 128 + fk * 2));
                *(uint32_t*)(hh + o0) = pack_f16x2(__float2half(h00), __float2half(h01));
                *(uint32_t*)(hh + o1) = pack_f16x2(__float2half(h10), __float2half(h11));
            }
        }
    }

    // ================= phase 2: GEMM2 (chunks 8..11) =================
    {
        const float* sB2 = (const float*)(smem + SM_B2);
        int c = 8;
        for (int nh = 0; nh < 2; nh++) {
            float acc2[8][4];
            #pragma unroll
            for (int t = 0; t < 8; t++)
                #pragma unroll
                for (int j = 0; j < 4; j++) acc2[t][j] = 0.f;

            #pragma unroll
            for (int c2 = 0; c2 < 2; c2++, c++) {
                if (c < 11) { CP_WAIT(1); } else { CP_WAIT(0); }
                __syncthreads();             // orders H writes (c==8) and buffer reuse
                if (c + 2 < 12) issue(c + 2);
                run_fused(acc2, HB(c2), WB(c % 3), arow0, br2, a_kad, b_kad);
            }

            const int r0 = 16 * wm + gid;
            #pragma unroll
            for (int t = 0; t < 8; t++) {
                const int col = nh * 256 + 64 * wn + 8 * t + 2 * tig;
                const float c0 = sB2[col], c1 = sB2[col + 1];
                if (r0 < rows) {
                    float2 v = { acc2[t][0] + c0, acc2[t][1] + c1 };
                    *(float2*)(out + (size_t)rowTok[r0] * DIM + col) = v;
                }
                if (r0 + 8 < rows) {
                    float2 v = { acc2[t][2] + c0, acc2[t][3] + c1 };
                    *(float2*)(out + (size_t)rowTok[r0 + 8] * DIM + col) = v;
                }
            }
        }
    }

    __syncthreads();
    if (tid == 0) cta_done_and_maybe_reset();
}

extern "C" void kernel_launch(void* const* d_in, const int* in_sizes, int n_in,
                              void* d_out, int out_size)
{
    const float* x   = (const float*)d_in[0];
    const float* wn0 = (const float*)d_in[2];
    const float* bn0 = (const float*)d_in[3];
    const float* wn1 = (const float*)d_in[4];
    const float* bn1 = (const float*)d_in[5];
    const float* wn2 = (const float*)d_in[6];
    const float* bn2 = (const float*)d_in[7];
    const float* w1a = (const float*)d_in[8];
    const float* b1a = (const float*)d_in[9];
    const float* w1b = (const float*)d_in[10];
    const float* b1b = (const float*)d_in[11];
    const float* w2  = (const float*)d_in[12];
    const float* b2  = (const float*)d_in[13];
    float* out = (float*)d_out;

    static_assert(SMEM_TOTAL <= 227 * 1024, "smem");
    cudaFuncSetAttribute(ffn_kernel, cudaFuncAttributeMaxDynamicSharedMemorySize, SMEM_TOTAL);

    // g_count is zero at entry: zero-initialized at module load, then re-zeroed by
    // ffn_kernel's last CTA on every launch (deterministic across graph replays).
    prep_route_kernel<<<2048, 256>>>(w1a, w1b, w2, x, wn0, bn0, wn1, bn1, wn2, bn2);
    dim3 grid(NLEAF, MAXTILES);
    ffn_kernel<<<grid, THREADS, SMEM_TOTAL>>>(b1a, b1b, b2, out);
}

// round 17
// speedup vs baseline: 1.7353x; 1.0009x over previous
#include <cuda_runtime.h>
#include <cuda_fp16.h>
#include <cstdint>

#define TOKENS   8192
#define DIM      512
#define FDIM     128
#define NLEAF    8
#define BM       64
#define MAXTILES 32
#define THREADS  512
#define TOTAL_CTAS (NLEAF * MAXTILES)

// ---------------- scratch ----------------
__device__ int g_count[NLEAF];          // zero-init at load; re-zeroed by ffn's last CTA
__device__ int g_done;                  // ffn completion counter (self-resetting)
__device__ int g_list[NLEAF * TOKENS];
__device__ __half g_x[TOKENS * DIM];    // fp16 activations
// W1 transposed fp16: [leaf][n=256][k=512]; n<128 -> w1a col n, n>=128 -> w1b col n-128
__device__ __half g_w1t[NLEAF * 256 * 512];
// W2 transposed fp16: [leaf][n=512][k=128]
__device__ __half g_w2t[NLEAF * 512 * 128];

__device__ __forceinline__ uint32_t smem_u32(const void* p) {
    uint32_t a;
    asm("{ .reg .u64 t; cvta.to.shared.u64 t, %1; cvt.u32.u64 %0, t; }" : "=r"(a) : "l"(p));
    return a;
}
__device__ __forceinline__ uint32_t sw128(uint32_t off) { return off ^ ((off >> 3) & 0x70); }

__device__ __forceinline__ uint32_t pack_f16x2(__half a, __half b) {
    union { __half h[2]; uint32_t u; } t;
    t.h[0] = a; t.h[1] = b;
    return t.u;
}

__device__ __forceinline__ void cpa16(uint32_t dst, const void* src) {
    asm volatile("cp.async.cg.shared.global [%0], [%1], 16;" :: "r"(dst), "l"(src) : "memory");
}
#define CP_COMMIT() asm volatile("cp.async.commit_group;" ::: "memory")
#define CP_WAIT(n)  asm volatile("cp.async.wait_group %0;" :: "n"(n) : "memory")

#define LDSM4(r, a)                                                                   \
    asm volatile("ldmatrix.sync.aligned.m8n8.x4.shared.b16 {%0,%1,%2,%3}, [%4];"     \
        : "=r"((r)[0]), "=r"((r)[1]), "=r"((r)[2]), "=r"((r)[3]) : "r"(a))

__device__ __forceinline__ void mma_f16(float* d, const uint32_t* a, uint32_t b0, uint32_t b1) {
    asm volatile(
        "mma.sync.aligned.m16n8k16.row.col.f32.f16.f16.f32 "
        "{%0,%1,%2,%3},{%4,%5,%6,%7},{%8,%9},{%0,%1,%2,%3};"
        : "+f"(d[0]), "+f"(d[1]), "+f"(d[2]), "+f"(d[3])
        : "r"(a[0]), "r"(a[1]), "r"(a[2]), "r"(a[3]), "r"(b0), "r"(b1));
}

// Single-pass fp16 k=64 sub-chunk, warp tile M16xN64: per kof -> 5 LDSM4, 8 HMMA.
__device__ __forceinline__ void run_fused(
    float acc[8][4], uint32_t A, uint32_t B,
    uint32_t arow0, const int br[4], int a_kad, int b_kad)
{
    #pragma unroll
    for (int kof = 0; kof < 64; kof += 16) {
        uint32_t af[4], bf[4][4];
        LDSM4(af, A + sw128(arow0 + (kof + a_kad) * 2));
        #pragma unroll
        for (int nt = 0; nt < 4; nt++)
            LDSM4(bf[nt], B + sw128((uint32_t)(br[nt] * 128 + (kof + b_kad) * 2)));
        #pragma unroll
        for (int nt = 0; nt < 4; nt++) {
            mma_f16(acc[2 * nt],     af, bf[nt][0], bf[nt][1]);
            mma_f16(acc[2 * nt + 1], af, bf[nt][2], bf[nt][3]);
        }
    }
}

__device__ __forceinline__ float warp_sum(float v) {
    #pragma unroll
    for (int o = 16; o > 0; o >>= 1) v += __shfl_xor_sync(0xFFFFFFFFu, v, o);
    return v;
}

// ---------------- fused prep (W transpose->fp16) + routing + X fp16 ----------------
// blocks [0,512): W1; [512,1024): W2; [1024,2048): route (8 tokens per block). 256 threads.
__global__ void prep_route_kernel(
    const float* __restrict__ w1a, const float* __restrict__ w1b, const float* __restrict__ w2,
    const float* __restrict__ x,
    const float* __restrict__ wn0, const float* __restrict__ bn0,
    const float* __restrict__ wn1, const float* __restrict__ bn1,
    const float* __restrict__ wn2, const float* __restrict__ bn2)
{
    const int bid = blockIdx.x;
    const int tid = threadIdx.x;

    if (bid < 512) {        // ---- W1: leaf/kt/ft ----
        const int leaf = bid >> 6, rem = bid & 63, kt = rem >> 2, ft = rem & 3;
        __shared__ float ta[32][33], tb[32][33];
        {
            int r = tid >> 3, cq = tid & 7;
            size_t src = ((size_t)leaf * 512 + kt * 32 + r) * 128 + ft * 32 + cq * 4;
            float4 va = *(const float4*)(w1a + src);
            float4 vb = *(const float4*)(w1b + src);
            ta[r][cq*4+0]=va.x; ta[r][cq*4+1]=va.y; ta[r][cq*4+2]=va.z; ta[r][cq*4+3]=va.w;
            tb[r][cq*4+0]=vb.x; tb[r][cq*4+1]=vb.y; tb[r][cq*4+2]=vb.z; tb[r][cq*4+3]=vb.w;
        }
        __syncthreads();
        {
            int n = tid >> 2, kq = tid & 3;
            int side = n >> 5, fl = n & 31;
            union { __half h[8]; uint4 u; } h8;
            #pragma unroll
            for (int j = 0; j < 8; j++) {
                float v = side ? tb[kq * 8 + j][fl] : ta[kq * 8 + j][fl];
                h8.h[j] = __float2half(v);
            }
            int orow = side ? (128 + ft * 32 + fl) : (ft * 32 + fl);
            size_t off = ((size_t)leaf * 256 + orow) * 512 + kt * 32 + kq * 8;
            *(uint4*)(g_w1t + off) = h8.u;
        }
    } else if (bid < 1024) {    // ---- W2: leaf/dt/kt ----
        const int b2i = bid - 512;
        const int leaf = b2i >> 6, rem = b2i & 63, dt = rem >> 2, kt = rem & 3;
        __shared__ float t[32][33];
        {
            int r = tid >> 3, cq = tid & 7;
            size_t src = ((size_t)leaf * 128 + kt * 32 + r) * 512 + dt * 32 + cq * 4;
            float4 v = *(const float4*)(w2 + src);
            t[r][cq*4+0]=v.x; t[r][cq*4+1]=v.y; t[r][cq*4+2]=v.z; t[r][cq*4+3]=v.w;
        }
        __syncthreads();
        {
            int n = tid >> 3, kq = tid & 7;
            union { __half h[4]; uint2 u; } h4;
            #pragma unroll
            for (int j = 0; j < 4; j++) h4.h[j] = __float2half(t[kq * 4 + j][n]);
            size_t orow = ((size_t)leaf * 512 + dt * 32 + n) * 128 + kt * 32 + kq * 4;
            *(uint2*)(g_w2t + orow) = h4.u;
        }
    } else {                // ---- route: one warp per token, single-pass 7 logits ----
        const int gwarp = (bid - 1024) * 8 + (tid >> 5);
        const int lane  = tid & 31;

        const float4* xr4 = (const float4*)(x + (size_t)gwarp * DIM);
        float4 xv[4];
        #pragma unroll
        for (int i = 0; i < 4; i++) xv[i] = xr4[lane + i * 32];

        {   // X fp16 write (reused by ffn via cp.async)
            __half* xh = g_x + (size_t)gwarp * DIM;
            #pragma unroll
            for (int i = 0; i < 4; i++) {
                union { __half h[4]; uint2 u; } h4;
                h4.h[0] = __float2half(xv[i].x);
                h4.h[1] = __float2half(xv[i].y);
                h4.h[2] = __float2half(xv[i].z);
                h4.h[3] = __float2half(xv[i].w);
                *(uint2*)(xh + (lane + i * 32) * 4) = h4.u;
            }
        }

        // all 7 node logits in one pass (s0; s1,s2 depth1; s3..s6 depth2)
        float s[7];
        #pragma unroll
        for (int j = 0; j < 7; j++) s[j] = 0.f;
        #pragma unroll
        for (int i = 0; i < 4; i++) {
            const int k4 = (lane + i * 32) * 4;
            const float4 v = xv[i];
            float4 w0 = *(const float4*)(wn0 + k4);
            s[0] += v.x * w0.x + v.y * w0.y + v.z * w0.z + v.w * w0.w;
            float4 wA = *(const float4*)(wn1 + k4 * 2);
            float4 wB = *(const float4*)(wn1 + k4 * 2 + 4);
            s[1] += v.x * wA.x + v.y * wA.z + v.z * wB.x + v.w * wB.z;
            s[2] += v.x * wA.y + v.y * wA.w + v.z * wB.y + v.w * wB.w;
            float4 w20 = *(const float4*)(wn2 + k4 * 4);
            float4 w21 = *(const float4*)(wn2 + k4 * 4 + 4);
            float4 w22 = *(const float4*)(wn2 + k4 * 4 + 8);
            float4 w23 = *(const float4*)(wn2 + k4 * 4 + 12);
            s[3] += v.x * w20.x + v.y * w21.x + v.z * w22.x + v.w * w23.x;
            s[4] += v.x * w20.y + v.y * w21.y + v.z * w22.y + v.w * w23.y;
            s[5] += v.x * w20.z + v.y * w21.z + v.z * w22.z + v.w * w23.z;
            s[6] += v.x * w20.w + v.y * w21.w + v.z * w22.w + v.w * w23.w;
        }
        #pragma unroll
        for (int j = 0; j < 7; j++) s[j] = warp_sum(s[j]);

        int node = ((s[0] + bn0[0]) > 0.f) ? 0 : 1;
        node = node * 2 + (((s[1 + node] + bn1[node]) > 0.f) ? 0 : 1);
        int leaf = node * 2 + (((s[3 + node] + bn2[node]) > 0.f) ? 0 : 1);

        if (lane == 0) {
            int pos = atomicAdd(&g_count[leaf], 1);
            g_list[leaf * TOKENS + pos] = gwarp;
        }
    }
}

// ---------------- SMEM layout: k=128 macro-chunks, 2-stage pipeline ----------------
#define SM_ROWTOK  0
#define SM_B1A     256
#define SM_B1B     768
#define SM_B2      1280                     // ends 3328
#define SM_X       4096                     // 2 buf x (2 sub x 8KB) = 32KB -> ends 36864
#define SM_W       36864                    // 2 buf x (2 sub x 32KB) = 128KB -> ends 167936
#define SM_H       167936                   // 2 x 8KB -> ends 184320
#define SMEM_TOTAL 184320

#define XB(p)  (sb + SM_X + (p) * 16384)
#define WB(p)  (sb + SM_W + (p) * 65536)
#define HB(k)  (sb + SM_H + (k) * 8192)

__device__ __forceinline__ void cta_done_and_maybe_reset() {
    int old = atomicAdd(&g_done, 1);
    if (old == TOTAL_CTAS - 1) {
        #pragma unroll
        for (int i = 0; i < NLEAF; i++) g_count[i] = 0;
        __threadfence();
        g_done = 0;
    }
}

// ---------------- fused leaf FFN: 6 macro-chunks, 16 warps, M16xN64 ----------------
__global__ void __launch_bounds__(THREADS, 1)
ffn_kernel(const float* __restrict__ b1a, const float* __restrict__ b1b,
           const float* __restrict__ b2,  float* __restrict__ out)
{
    extern __shared__ char smem[];
    const uint32_t sb = smem_u32(smem);
    const int tid  = threadIdx.x;
    const int wid  = tid >> 5;
    const int lane = tid & 31;

    const int leaf  = blockIdx.x;
    const int cnt   = g_count[leaf];
    const int start = blockIdx.y * BM;
    if (start >= cnt) {
        __syncthreads();
        if (tid == 0) cta_done_and_maybe_reset();
        return;
    }
    const int rows = min(BM, cnt - start);
    const int* list = g_list + leaf * TOKENS + start;

    int* rowTok = (int*)(smem + SM_ROWTOK);
    if (tid < BM) rowTok[tid] = list[min(tid, rows - 1)];
    {
        float* sB1a = (float*)(smem + SM_B1A);
        float* sB1b = (float*)(smem + SM_B1B);
        float* sB2  = (float*)(smem + SM_B2);
        if (tid < FDIM) { sB1a[tid] = b1a[leaf * FDIM + tid]; sB1b[tid] = b1b[leaf * FDIM + tid]; }
        if (tid < DIM)  sB2[tid] = b2[leaf * DIM + tid];
    }
    __syncthreads();

    const int wm = wid & 3;        // m-block: rows 16*wm..+15
    const int wn = wid >> 2;       // n-block 0..3
    const int gid = lane >> 2, tig = lane & 3;
    const int a_row = lane & 15;
    const int a_kad = (lane & 16) >> 1;
    const int b_row = (lane & 7) | ((lane >> 1) & 8);
    const int b_kad = lane & 8;
    const uint32_t arow0 = (uint32_t)((16 * wm + a_row) * 128);

    const int br1[4] = { 32 * wn + b_row, 32 * wn + 16 + b_row,
                         128 + 32 * wn + b_row, 128 + 32 * wn + 16 + b_row };
    const int br2[4] = { 64 * wn + b_row, 64 * wn + 16 + b_row,
                         64 * wn + 32 + b_row, 64 * wn + 48 + b_row };

    // loaders: X one 16B per thread per sub; W 4 per thread per sub
    const int xq = tid & 7;
    const size_t tokA = (size_t)rowTok[tid >> 3] * DIM;
    const __half* w1base = g_w1t + (size_t)leaf * 256 * DIM;
    const __half* w2base = g_w2t + (size_t)leaf * 512 * FDIM;

    // macro-chunk c: 0..3 = GEMM1 (k0 = c*128), 4..5 = GEMM2 (nh = c-4)
    auto issue = [&](int c) {
        const int p = c & 1;
        if (c < 4) {
            const int k0 = c * 128;
            #pragma unroll
            for (int s = 0; s < 2; s++) {
                uint32_t so = sw128((uint32_t)((tid >> 3) * 128 + xq * 16));
                cpa16(XB(p) + s * 8192 + so, g_x + tokA + k0 + s * 64 + xq * 8);
                const __half* wb = w1base + k0 + s * 64;
                #pragma unroll
                for (int it = 0; it < 4; it++) {      // W1 sub: 256 rows x 128B
                    int idx = tid + it * THREADS;
                    int wrow = idx >> 3, q = idx & 7;
                    uint32_t wo = sw128((uint32_t)(wrow * 128 + q * 16));
                    cpa16(WB(p) + s * 32768 + wo, wb + (size_t)wrow * DIM + q * 8);
                }
            }
        } else {
            const int nh = c - 4;
            #pragma unroll
            for (int s = 0; s < 2; s++) {
                const __half* wb = w2base + (size_t)nh * 256 * FDIM + s * 64;
                #pragma unroll
                for (int it = 0; it < 4; it++) {
                    int idx = tid + it * THREADS;
                    int wrow = idx >> 3, q = idx & 7;
                    uint32_t wo = sw128((uint32_t)(wrow * 128 + q * 16));
                    cpa16(WB(p) + s * 32768 + wo, wb + (size_t)wrow * FDIM + q * 8);
                }
            }
        }
        CP_COMMIT();
    };

    issue(0);

    // ================= phase 1: GEMM1 (macro-chunks 0..3) =================
    {
        float acc[8][4];
        #pragma unroll
        for (int t = 0; t < 8; t++)
            #pragma unroll
            for (int j = 0; j < 4; j++) acc[t][j] = 0.f;

        for (int c = 0; c < 4; c++) {
            const int p = c & 1;
            CP_WAIT(0);                      // chunk c landed (only group outstanding)
            __syncthreads();                 // all warps past run_fused(c-1)
            issue(c + 1);                    // other buffer, free after barrier
            run_fused(acc, XB(p),        WB(p),         arow0, br1, a_kad, b_kad);
            run_fused(acc, XB(p) + 8192, WB(p) + 32768, arow0, br1, a_kad, b_kad);
        }

        // epilogue1: gate (a tile nt, b tile nt+2) -> H fp16, packed 4B stores
        const float* sB1a = (const float*)(smem + SM_B1A);
        const float* sB1b = (const float*)(smem + SM_B1B);
        const int r0 = 16 * wm + gid;
        #pragma unroll
        for (int nt = 0; nt < 2; nt++) {
            #pragma unroll
            for (int q = 0; q < 2; q++) {
                const int f = 32 * wn + 16 * nt + 8 * q + 2 * tig;
                const float* A = acc[2 * nt + q];
                const float* G = acc[2 * (nt + 2) + q];
                const float ba0 = sB1a[f], ba1 = sB1a[f + 1];
                const float bb0 = sB1b[f], bb1 = sB1b[f + 1];
                const float h00 = (A[0] + ba0) * (G[0] + bb0);
                const float h01 = (A[1] + ba1) * (G[1] + bb1);
                const float h10 = (A[2] + ba0) * (G[2] + bb0);
                const float h11 = (A[3] + ba1) * (G[3] + bb1);
                const int kc = f >> 6, fk = f & 63;
                char* hh = smem + (HB(kc) - sb);
                const uint32_t o0 = sw128((uint32_t)(r0 * 128 + fk * 2));
                const uint32_t o1 = sw128((uint32_t)((r0 + 8) * 128 + fk * 2));
                *(uint32_t*)(hh + o0) = pack_f16x2(__float2half(h00), __float2half(h01));
                *(uint32_t*)(hh + o1) = pack_f16x2(__float2half(h10), __float2half(h11));
            }
        }
    }

    // ================= phase 2: GEMM2 (macro-chunks 4..5, nh = c-4) =================
    {
        const float* sB2 = (const float*)(smem + SM_B2);
        for (int nh = 0; nh < 2; nh++) {
            const int c = 4 + nh, p = c & 1;
            float acc2[8][4];
            #pragma unroll
            for (int t = 0; t < 8; t++)
                #pragma unroll
                for (int j = 0; j < 4; j++) acc2[t][j] = 0.f;

            CP_WAIT(0);
            __syncthreads();                 // orders H writes (nh==0) and buffer reuse
            if (c + 1 < 6) issue(c + 1);
            run_fused(acc2, HB(0), WB(p),         arow0, br2, a_kad, b_kad);
            run_fused(acc2, HB(1), WB(p) + 32768, arow0, br2, a_kad, b_kad);

            const int r0 = 16 * wm + gid;
            #pragma unroll
            for (int t = 0; t < 8; t++) {
                const int col = nh * 256 + 64 * wn + 8 * t + 2 * tig;
                const float c0 = sB2[col], c1 = sB2[col + 1];
                if (r0 < rows) {
                    float2 v = { acc2[t][0] + c0, acc2[t][1] + c1 };
                    *(float2*)(out + (size_t)rowTok[r0] * DIM + col) = v;
                }
                if (r0 + 8 < rows) {
                    float2 v = { acc2[t][2] + c0, acc2[t][3] + c1 };
                    *(float2*)(out + (size_t)rowTok[r0 + 8] * DIM + col) = v;
                }
            }
        }
    }

    __syncthreads();
    if (tid == 0) cta_done_and_maybe_reset();
}

extern "C" void kernel_launch(void* const* d_in, const int* in_sizes, int n_in,
                              void* d_out, int out_size)
{
    const float* x   = (const float*)d_in[0];
    const float* wn0 = (const float*)d_in[2];
    const float* bn0 = (const float*)d_in[3];
    const float* wn1 = (const float*)d_in[4];
    const float* bn1 = (const float*)d_in[5];
    const float* wn2 = (const float*)d_in[6];
    const float* bn2 = (const float*)d_in[7];
    const float* w1a = (const float*)d_in[8];
    const float* b1a = (const float*)d_in[9];
    const float* w1b = (const float*)d_in[10];
    const float* b1b = (const float*)d_in[11];
    const float* w2  = (const float*)d_in[12];
    const float* b2  = (const float*)d_in[13];
    float* out = (float*)d_out;

    static_assert(SMEM_TOTAL <= 227 * 1024, "smem");
    cudaFuncSetAttribute(ffn_kernel, cudaFuncAttributeMaxDynamicSharedMemorySize, SMEM_TOTAL);

    // g_count is zero at entry: zero-initialized at module load, then re-zeroed by
    // ffn_kernel's last CTA on every launch (deterministic across graph replays).
    prep_route_kernel<<<2048, 256>>>(w1a, w1b, w2, x, wn0, bn0, wn1, bn1, wn2, bn2);
    dim3 grid(NLEAF, MAXTILES);
    ffn_kernel<<<grid, THREADS, SMEM_TOTAL>>>(b1a, b1b, b2, out);
}